// round 1
// baseline (speedup 1.0000x reference)
#include <cuda_runtime.h>
#include <cuda_bf16.h>

#define N_B   256
#define D_K   1024
#define C_DIM 50000
#define G_N   4
#define NNZ_G 300000
#define E_TOT (G_N * NNZ_G)

// ---------------- scratch (static __device__, no allocs) ----------------
__device__ float g_mean[D_K];
__device__ float g_rstd[D_K];
__device__ float g_h0t[D_K * N_B];          // h0 transposed: [K, M], m contiguous
__device__ float g_Zt[(size_t)C_DIM * N_B]; // Z transposed:  [C, N]
__device__ float g_NT[(size_t)C_DIM * N_B]; // neighbors+Z transposed accumulator

// ---------------- kernel 1: batch stats (mean, rstd) --------------------
__global__ void stats_kernel(const float* __restrict__ x) {
    int tx = threadIdx.x & 31, ty = threadIdx.x >> 5;
    int c = blockIdx.x * 32 + tx;
    float s = 0.f, sq = 0.f;
    for (int r = ty; r < N_B; r += 8) {
        float v = x[r * D_K + c];
        s += v; sq += v * v;
    }
    __shared__ float ss[8][32], s2[8][32];
    ss[ty][tx] = s; s2[ty][tx] = sq;
    __syncthreads();
    if (ty == 0) {
        #pragma unroll
        for (int j = 1; j < 8; j++) { s += ss[j][tx]; sq += s2[j][tx]; }
        float mean = s * (1.f / N_B);
        float var  = sq * (1.f / N_B) - mean * mean;
        g_mean[c] = mean;
        g_rstd[c] = rsqrtf(var + 1e-5f);
    }
}

// ---------------- kernel 2: normalize + transpose -> h0t [K, M] ---------
__global__ void norm_t_kernel(const float* __restrict__ x) {
    __shared__ float tile[32][33];
    int k0 = blockIdx.x * 32, m0 = blockIdx.y * 32;
    int tx = threadIdx.x & 31, ty = threadIdx.x >> 5;
    for (int j = ty; j < 32; j += 8)
        tile[j][tx] = x[(m0 + j) * D_K + k0 + tx];   // tile[m_local][k_local]
    __syncthreads();
    for (int j = ty; j < 32; j += 8) {
        int k = k0 + j;
        g_h0t[k * N_B + m0 + tx] = (tile[tx][j] - g_mean[k]) * g_rstd[k];
    }
}

// ---------------- kernel 3: GEMM + bias + swish -> Zt, NT ---------------
// Zt[c][m] = swish( sum_k W[c][k] * h0t[k][m] + b[c] )
#define BC 128
#define BM 128
#define BK 16

__global__ __launch_bounds__(256, 2) void gemm_kernel(
        const float* __restrict__ W, const float* __restrict__ bias) {
    __shared__ float Ws[BK][BC + 4];  // [kk][c]
    __shared__ float Hs[BK][BM];      // [kk][m]
    int c0 = blockIdx.x * BC;
    int m0 = blockIdx.y * BM;
    int tid = threadIdx.x;
    int tm = tid & 15, tc = tid >> 4;   // 16 x 16 thread grid, 8x8 micro-tile

    unsigned long long acc[8][4];
    #pragma unroll
    for (int i = 0; i < 8; i++)
        #pragma unroll
        for (int j = 0; j < 4; j++) acc[i][j] = 0ULL;

    const float* Hbase = g_h0t + m0;

    for (int k0 = 0; k0 < D_K; k0 += BK) {
        // load W tile [BC x BK] -> Ws transposed [BK][BC]
        #pragma unroll
        for (int l = 0; l < 2; l++) {
            int id  = tid + l * 256;
            int row = id >> 2, k4 = id & 3;
            int c = c0 + row;
            float4 v = make_float4(0.f, 0.f, 0.f, 0.f);
            if (c < C_DIM)
                v = *(const float4*)(W + (size_t)c * D_K + k0 + k4 * 4);
            Ws[k4 * 4 + 0][row] = v.x;
            Ws[k4 * 4 + 1][row] = v.y;
            Ws[k4 * 4 + 2][row] = v.z;
            Ws[k4 * 4 + 3][row] = v.w;
        }
        // load H tile [BK x BM]
        #pragma unroll
        for (int l = 0; l < 2; l++) {
            int id = tid + l * 256;
            int kk = id >> 5, m4 = id & 31;
            float4 v = *(const float4*)(Hbase + (k0 + kk) * N_B + m4 * 4);
            *(float4*)&Hs[kk][m4 * 4] = v;
        }
        __syncthreads();

        #pragma unroll
        for (int kk = 0; kk < BK; kk++) {
            unsigned long long b[4];
            const unsigned long long* hrow =
                (const unsigned long long*)&Hs[kk][tm * 8];
            #pragma unroll
            for (int j = 0; j < 4; j++) b[j] = hrow[j];
            #pragma unroll
            for (int i = 0; i < 8; i++) {
                float a = Ws[kk][tc * 8 + i];
                unsigned long long ap;
                asm("mov.b64 %0, {%1, %1};" : "=l"(ap) : "f"(a));
                #pragma unroll
                for (int j = 0; j < 4; j++)
                    asm("fma.rn.f32x2 %0, %1, %2, %0;"
                        : "+l"(acc[i][j]) : "l"(ap), "l"(b[j]));
            }
        }
        __syncthreads();
    }

    // epilogue: bias + swish, write Zt (gather source) and NT (accumulator init)
    #pragma unroll
    for (int i = 0; i < 8; i++) {
        int c = c0 + tc * 8 + i;
        if (c >= C_DIM) continue;
        float bv = bias[c];
        float vals[8];
        #pragma unroll
        for (int j = 0; j < 4; j++) {
            float lo, hi;
            asm("mov.b64 {%0, %1}, %2;" : "=f"(lo), "=f"(hi) : "l"(acc[i][j]));
            float h1 = lo + bv, h2 = hi + bv;
            vals[2 * j]     = h1 * (1.f / (1.f + __expf(-h1)));
            vals[2 * j + 1] = h2 * (1.f / (1.f + __expf(-h2)));
        }
        size_t base = (size_t)c * N_B + m0 + tm * 8;
        float4 v0 = make_float4(vals[0], vals[1], vals[2], vals[3]);
        float4 v1 = make_float4(vals[4], vals[5], vals[6], vals[7]);
        *(float4*)(g_Zt + base)     = v0;
        *(float4*)(g_Zt + base + 4) = v1;
        *(float4*)(g_NT + base)     = v0;
        *(float4*)(g_NT + base + 4) = v1;
    }
}

// ---------------- kernel 4: edge scatter (warp per edge) ----------------
__global__ void scatter_kernel(const float* __restrict__ A_vals,
                               const float* __restrict__ vec,
                               const int* __restrict__ A_rows,
                               const int* __restrict__ A_cols) {
    int warp = (blockIdx.x * blockDim.x + threadIdx.x) >> 5;
    int lane = threadIdx.x & 31;
    if (warp >= E_TOT) return;
    int g = warp / NNZ_G;
    float w = A_vals[warp] * vec[g];
    int col = A_cols[warp];
    int row = A_rows[warp];
    const float4* src = (const float4*)(g_Zt + (size_t)col * N_B);
    float*        dst = g_NT + (size_t)row * N_B;
    #pragma unroll
    for (int j = 0; j < 2; j++) {
        float4 v = src[lane + 32 * j];
        int o = (lane + 32 * j) * 4;
        atomicAdd(dst + o + 0, v.x * w);
        atomicAdd(dst + o + 1, v.y * w);
        atomicAdd(dst + o + 2, v.z * w);
        atomicAdd(dst + o + 3, v.w * w);
    }
}

// ---------------- kernel 5: transpose NT -> out [N, C] ------------------
__global__ void out_kernel(float* __restrict__ out) {
    __shared__ float tile[32][33];
    int c0 = blockIdx.x * 32, b0 = blockIdx.y * 32;
    int tx = threadIdx.x & 31, ty = threadIdx.x >> 5;
    for (int j = ty; j < 32; j += 8) {
        int c = c0 + j;
        tile[j][tx] = (c < C_DIM) ? g_NT[(size_t)c * N_B + b0 + tx] : 0.f;
    }
    __syncthreads();
    for (int j = ty; j < 32; j += 8) {
        int c = c0 + tx;
        if (c < C_DIM)
            out[(size_t)(b0 + j) * C_DIM + c] = tile[tx][j];
    }
}

// ---------------- launch ------------------------------------------------
extern "C" void kernel_launch(void* const* d_in, const int* in_sizes, int n_in,
                              void* d_out, int out_size) {
    const float* output = (const float*)d_in[0];
    const float* wt2_w  = (const float*)d_in[1];
    const float* wt2_b  = (const float*)d_in[2];
    const float* A_vals = (const float*)d_in[3];
    const float* vec    = (const float*)d_in[4];
    const int*   A_rows = (const int*)d_in[5];
    const int*   A_cols = (const int*)d_in[6];
    float* out = (float*)d_out;

    stats_kernel<<<D_K / 32, 256>>>(output);
    norm_t_kernel<<<dim3(D_K / 32, N_B / 32), 256>>>(output);
    gemm_kernel<<<dim3((C_DIM + BC - 1) / BC, N_B / BM), 256>>>(wt2_w, wt2_b);
    scatter_kernel<<<(E_TOT * 32) / 256, 256>>>(A_vals, vec, A_rows, A_cols);
    out_kernel<<<dim3((C_DIM + 31) / 32, N_B / 32), 256>>>(out);
}

// round 2
// speedup vs baseline: 1.6992x; 1.6992x over previous
#include <cuda_runtime.h>
#include <cuda_bf16.h>

#define N_B   256
#define D_K   1024
#define C_DIM 50000
#define G_N   4
#define NNZ_G 300000
#define E_TOT (G_N * NNZ_G)
#define NBLK_SCAN ((C_DIM + 255) / 256)   // 196

// ---------------- scratch (static __device__, no allocs) ----------------
__device__ float g_mean[D_K];
__device__ float g_rstd[D_K];
__device__ float g_h0t[D_K * N_B];          // h0 transposed: [K, M]
__device__ float g_Zt[(size_t)C_DIM * N_B]; // Z transposed:  [C, N]
__device__ float g_NT[(size_t)C_DIM * N_B]; // neighbors+Z transposed

// CSR build scratch
__device__ int   g_cnt[C_DIM];
__device__ int   g_local[C_DIM];
__device__ int   g_bsum[256];
__device__ int   g_boff[256];
__device__ int   g_rowstart[C_DIM + 1];
__device__ int   g_cursor[C_DIM];
__device__ int   g_ecol[E_TOT];
__device__ float g_ew[E_TOT];

// ---------------- kernel 1: batch stats (mean, rstd) --------------------
__global__ void stats_kernel(const float* __restrict__ x) {
    int tx = threadIdx.x & 31, ty = threadIdx.x >> 5;
    int c = blockIdx.x * 32 + tx;
    float s = 0.f, sq = 0.f;
    for (int r = ty; r < N_B; r += 8) {
        float v = x[r * D_K + c];
        s += v; sq += v * v;
    }
    __shared__ float ss[8][32], s2[8][32];
    ss[ty][tx] = s; s2[ty][tx] = sq;
    __syncthreads();
    if (ty == 0) {
        #pragma unroll
        for (int j = 1; j < 8; j++) { s += ss[j][tx]; sq += s2[j][tx]; }
        float mean = s * (1.f / N_B);
        float var  = sq * (1.f / N_B) - mean * mean;
        g_mean[c] = mean;
        g_rstd[c] = rsqrtf(var + 1e-5f);
    }
}

// ---------------- kernel 2: normalize + transpose -> h0t [K, M] ---------
__global__ void norm_t_kernel(const float* __restrict__ x) {
    __shared__ float tile[32][33];
    int k0 = blockIdx.x * 32, m0 = blockIdx.y * 32;
    int tx = threadIdx.x & 31, ty = threadIdx.x >> 5;
    for (int j = ty; j < 32; j += 8)
        tile[j][tx] = x[(m0 + j) * D_K + k0 + tx];
    __syncthreads();
    for (int j = ty; j < 32; j += 8) {
        int k = k0 + j;
        g_h0t[k * N_B + m0 + tx] = (tile[tx][j] - g_mean[k]) * g_rstd[k];
    }
}

// ---------------- kernel 3: GEMM + bias + swish -> Zt -------------------
#define BC 128
#define BM 128
#define BK 16

__global__ __launch_bounds__(256, 2) void gemm_kernel(
        const float* __restrict__ W, const float* __restrict__ bias) {
    __shared__ float Ws[BK][BC + 4];
    __shared__ float Hs[BK][BM];
    int c0 = blockIdx.x * BC;
    int m0 = blockIdx.y * BM;
    int tid = threadIdx.x;
    int tm = tid & 15, tc = tid >> 4;

    unsigned long long acc[8][4];
    #pragma unroll
    for (int i = 0; i < 8; i++)
        #pragma unroll
        for (int j = 0; j < 4; j++) acc[i][j] = 0ULL;

    const float* Hbase = g_h0t + m0;

    for (int k0 = 0; k0 < D_K; k0 += BK) {
        #pragma unroll
        for (int l = 0; l < 2; l++) {
            int id  = tid + l * 256;
            int row = id >> 2, k4 = id & 3;
            int c = c0 + row;
            float4 v = make_float4(0.f, 0.f, 0.f, 0.f);
            if (c < C_DIM)
                v = *(const float4*)(W + (size_t)c * D_K + k0 + k4 * 4);
            Ws[k4 * 4 + 0][row] = v.x;
            Ws[k4 * 4 + 1][row] = v.y;
            Ws[k4 * 4 + 2][row] = v.z;
            Ws[k4 * 4 + 3][row] = v.w;
        }
        #pragma unroll
        for (int l = 0; l < 2; l++) {
            int id = tid + l * 256;
            int kk = id >> 5, m4 = id & 31;
            float4 v = *(const float4*)(Hbase + (k0 + kk) * N_B + m4 * 4);
            *(float4*)&Hs[kk][m4 * 4] = v;
        }
        __syncthreads();

        #pragma unroll
        for (int kk = 0; kk < BK; kk++) {
            unsigned long long b[4];
            const unsigned long long* hrow =
                (const unsigned long long*)&Hs[kk][tm * 8];
            #pragma unroll
            for (int j = 0; j < 4; j++) b[j] = hrow[j];
            #pragma unroll
            for (int i = 0; i < 8; i++) {
                float a = Ws[kk][tc * 8 + i];
                unsigned long long ap;
                asm("mov.b64 %0, {%1, %1};" : "=l"(ap) : "f"(a));
                #pragma unroll
                for (int j = 0; j < 4; j++)
                    asm("fma.rn.f32x2 %0, %1, %2, %0;"
                        : "+l"(acc[i][j]) : "l"(ap), "l"(b[j]));
            }
        }
        __syncthreads();
    }

    #pragma unroll
    for (int i = 0; i < 8; i++) {
        int c = c0 + tc * 8 + i;
        if (c >= C_DIM) continue;
        float bv = bias[c];
        float vals[8];
        #pragma unroll
        for (int j = 0; j < 4; j++) {
            float lo, hi;
            asm("mov.b64 {%0, %1}, %2;" : "=f"(lo), "=f"(hi) : "l"(acc[i][j]));
            float h1 = lo + bv, h2 = hi + bv;
            vals[2 * j]     = h1 * (1.f / (1.f + __expf(-h1)));
            vals[2 * j + 1] = h2 * (1.f / (1.f + __expf(-h2)));
        }
        size_t base = (size_t)c * N_B + m0 + tm * 8;
        *(float4*)(g_Zt + base)     = make_float4(vals[0], vals[1], vals[2], vals[3]);
        *(float4*)(g_Zt + base + 4) = make_float4(vals[4], vals[5], vals[6], vals[7]);
    }
}

// ---------------- CSR build: zero, hist, scan x3, bucket-scatter --------
__global__ void zero_cnt_kernel() {
    int i = blockIdx.x * 256 + threadIdx.x;
    if (i < C_DIM) g_cnt[i] = 0;
}

__global__ void hist_kernel(const int* __restrict__ A_rows) {
    int e = blockIdx.x * 256 + threadIdx.x;
    if (e < E_TOT) atomicAdd(&g_cnt[A_rows[e]], 1);
}

__global__ void scan1_kernel() {
    int i = blockIdx.x * 256 + threadIdx.x;
    int v = (i < C_DIM) ? g_cnt[i] : 0;
    int lane = threadIdx.x & 31, w = threadIdx.x >> 5;
    int x = v;
    #pragma unroll
    for (int o = 1; o < 32; o <<= 1) {
        int y = __shfl_up_sync(~0u, x, o);
        if (lane >= o) x += y;
    }
    __shared__ int ws[8];
    if (lane == 31) ws[w] = x;
    __syncthreads();
    if (threadIdx.x < 8) {
        int s = ws[threadIdx.x];
        #pragma unroll
        for (int o = 1; o < 8; o <<= 1) {
            int y = __shfl_up_sync(0xff, s, o);
            if ((int)threadIdx.x >= o) s += y;
        }
        ws[threadIdx.x] = s;
    }
    __syncthreads();
    int off = (w > 0) ? ws[w - 1] : 0;
    int incl = x + off;
    if (i < C_DIM) g_local[i] = incl - v;     // exclusive within block
    if (threadIdx.x == 255) g_bsum[blockIdx.x] = incl;
}

__global__ void scan2_kernel() {                 // 1 block, 256 threads
    int i = threadIdx.x;
    int v = (i < NBLK_SCAN) ? g_bsum[i] : 0;
    int lane = i & 31, w = i >> 5;
    int x = v;
    #pragma unroll
    for (int o = 1; o < 32; o <<= 1) {
        int y = __shfl_up_sync(~0u, x, o);
        if (lane >= o) x += y;
    }
    __shared__ int ws[8];
    if (lane == 31) ws[w] = x;
    __syncthreads();
    if (i < 8) {
        int s = ws[i];
        #pragma unroll
        for (int o = 1; o < 8; o <<= 1) {
            int y = __shfl_up_sync(0xff, s, o);
            if (i >= o) s += y;
        }
        ws[i] = s;
    }
    __syncthreads();
    int off = (w > 0) ? ws[w - 1] : 0;
    g_boff[i] = x + off - v;                     // exclusive
}

__global__ void scan3_kernel() {
    int i = blockIdx.x * 256 + threadIdx.x;
    if (i < C_DIM) {
        int rs = g_local[i] + g_boff[i >> 8];
        g_rowstart[i] = rs;
        g_cursor[i]   = rs;
    }
    if (i == 0) g_rowstart[C_DIM] = E_TOT;
}

__global__ void build_kernel(const float* __restrict__ A_vals,
                             const float* __restrict__ vec,
                             const int* __restrict__ A_rows,
                             const int* __restrict__ A_cols) {
    int e = blockIdx.x * 256 + threadIdx.x;
    if (e >= E_TOT) return;
    int r = A_rows[e];
    int pos = atomicAdd(&g_cursor[r], 1);
    g_ecol[pos] = A_cols[e];
    g_ew[pos]   = A_vals[e] * __ldg(&vec[e / NNZ_G]);
}

// ---------------- SpMM: 64-thread group per row, register accumulate ----
__global__ __launch_bounds__(256) void spmm_kernel() {
    int row = blockIdx.x * 4 + (threadIdx.x >> 6);
    int t   = threadIdx.x & 63;
    if (row >= C_DIM) return;
    int beg = g_rowstart[row], end = g_rowstart[row + 1];
    const float4* Z4 = (const float4*)g_Zt;

    float4 acc = Z4[(size_t)row * 64 + t];       // residual Z init
    int e = beg;
    for (; e + 1 < end; e += 2) {
        int   c0 = g_ecol[e],     c1 = g_ecol[e + 1];
        float w0 = g_ew[e],       w1 = g_ew[e + 1];
        float4 v0 = Z4[(size_t)c0 * 64 + t];
        float4 v1 = Z4[(size_t)c1 * 64 + t];
        acc.x = fmaf(w0, v0.x, acc.x); acc.y = fmaf(w0, v0.y, acc.y);
        acc.z = fmaf(w0, v0.z, acc.z); acc.w = fmaf(w0, v0.w, acc.w);
        acc.x = fmaf(w1, v1.x, acc.x); acc.y = fmaf(w1, v1.y, acc.y);
        acc.z = fmaf(w1, v1.z, acc.z); acc.w = fmaf(w1, v1.w, acc.w);
    }
    if (e < end) {
        int   c0 = g_ecol[e];
        float w0 = g_ew[e];
        float4 v0 = Z4[(size_t)c0 * 64 + t];
        acc.x = fmaf(w0, v0.x, acc.x); acc.y = fmaf(w0, v0.y, acc.y);
        acc.z = fmaf(w0, v0.z, acc.z); acc.w = fmaf(w0, v0.w, acc.w);
    }
    ((float4*)g_NT)[(size_t)row * 64 + t] = acc;
}

// ---------------- transpose NT -> out [N, C] ----------------------------
__global__ void out_kernel(float* __restrict__ out) {
    __shared__ float tile[32][33];
    int c0 = blockIdx.x * 32, b0 = blockIdx.y * 32;
    int tx = threadIdx.x & 31, ty = threadIdx.x >> 5;
    for (int j = ty; j < 32; j += 8) {
        int c = c0 + j;
        tile[j][tx] = (c < C_DIM) ? g_NT[(size_t)c * N_B + b0 + tx] : 0.f;
    }
    __syncthreads();
    for (int j = ty; j < 32; j += 8) {
        int c = c0 + tx;
        if (c < C_DIM)
            out[(size_t)(b0 + j) * C_DIM + c] = tile[tx][j];
    }
}

// ---------------- launch ------------------------------------------------
extern "C" void kernel_launch(void* const* d_in, const int* in_sizes, int n_in,
                              void* d_out, int out_size) {
    const float* output = (const float*)d_in[0];
    const float* wt2_w  = (const float*)d_in[1];
    const float* wt2_b  = (const float*)d_in[2];
    const float* A_vals = (const float*)d_in[3];
    const float* vec    = (const float*)d_in[4];
    const int*   A_rows = (const int*)d_in[5];
    const int*   A_cols = (const int*)d_in[6];
    float* out = (float*)d_out;

    int egrid = (E_TOT + 255) / 256;

    // CSR build (independent of GEMM chain)
    zero_cnt_kernel<<<NBLK_SCAN, 256>>>();
    hist_kernel<<<egrid, 256>>>(A_rows);
    scan1_kernel<<<NBLK_SCAN, 256>>>();
    scan2_kernel<<<1, 256>>>();
    scan3_kernel<<<NBLK_SCAN, 256>>>();
    build_kernel<<<egrid, 256>>>(A_vals, vec, A_rows, A_cols);

    // dense chain
    stats_kernel<<<D_K / 32, 256>>>(output);
    norm_t_kernel<<<dim3(D_K / 32, N_B / 32), 256>>>(output);
    gemm_kernel<<<dim3((C_DIM + BC - 1) / BC, N_B / BM), 256>>>(wt2_w, wt2_b);

    // sparse aggregate + residual, then transpose out
    spmm_kernel<<<(C_DIM + 3) / 4, 256>>>();
    out_kernel<<<dim3((C_DIM + 31) / 32, N_B / 32), 256>>>(out);
}

// round 4
// speedup vs baseline: 2.9548x; 1.7389x over previous
#include <cuda_runtime.h>
#include <cuda_bf16.h>
#include <cstdint>

#define N_B   256
#define D_K   1024
#define C_DIM 50000
#define G_N   4
#define NNZ_G 300000
#define E_TOT (G_N * NNZ_G)
#define NBLK_SCAN ((C_DIM + 255) / 256)   // 196

#define KC    32
#define NCH   (D_K / KC)                  // 32
#define TILE_C 128
#define NTILES ((C_DIM + TILE_C - 1) / TILE_C)  // 391
#define GEMM_SMEM 65536                   // (A 16K + B 16K) x 2 stages

// ---------------- scratch (static __device__, no allocs) ----------------
__device__ float g_mean[D_K];
__device__ float g_rstd[D_K];
__device__ float g_Zt[(size_t)C_DIM * N_B]; // Z transposed:  [C, N]
__device__ float g_NT[(size_t)C_DIM * N_B]; // neighbors+Z transposed
// B images: per chunk, 256 m-rows of 128B = [hi k0..31 (64B) | lo (64B)], swizzled
__device__ unsigned char g_B[NCH * N_B * 128];

// CSR build scratch
__device__ int   g_cnt[C_DIM];
__device__ int   g_local[C_DIM];
__device__ int   g_bsum[256];
__device__ int   g_boff[256];
__device__ int   g_rowstart[C_DIM + 1];
__device__ int   g_cursor[C_DIM];
__device__ int   g_ecol[E_TOT];
__device__ float g_ew[E_TOT];

// ---------------- helpers ----------------------------------------------
__device__ __forceinline__ uint32_t smem_u32(const void* p) {
    uint32_t a;
    asm("{ .reg .u64 t; cvta.to.shared.u64 t, %1; cvt.u32.u64 %0, t; }"
        : "=r"(a) : "l"(p));
    return a;
}
#define SW128(o) ((o) ^ (((o) >> 3) & 0x70))

#define LDSM4(f, addr) \
    asm volatile("ldmatrix.sync.aligned.m8n8.x4.shared.b16 {%0,%1,%2,%3}, [%4];" \
        : "=r"((f)[0]), "=r"((f)[1]), "=r"((f)[2]), "=r"((f)[3]) : "r"(addr))
#define LDSM2(f, addr) \
    asm volatile("ldmatrix.sync.aligned.m8n8.x2.shared.b16 {%0,%1}, [%2];" \
        : "=r"((f)[0]), "=r"((f)[1]) : "r"(addr))
#define MMA16816(d, a, b) \
    asm volatile("mma.sync.aligned.m16n8k16.row.col.f32.bf16.bf16.f32 " \
        "{%0,%1,%2,%3}, {%4,%5,%6,%7}, {%8,%9}, {%0,%1,%2,%3};" \
        : "+f"((d)[0]), "+f"((d)[1]), "+f"((d)[2]), "+f"((d)[3]) \
        : "r"((a)[0]), "r"((a)[1]), "r"((a)[2]), "r"((a)[3]), \
          "r"((b)[0]), "r"((b)[1]))
#define CP_ASYNC16(dst, src) \
    asm volatile("cp.async.cg.shared.global [%0], [%1], 16;" :: "r"(dst), "l"(src))
#define CP_COMMIT() asm volatile("cp.async.commit_group;" ::: "memory")
#define CP_WAIT0()  asm volatile("cp.async.wait_group 0;"  ::: "memory")

__device__ __forceinline__ uint32_t pack2(float a, float b) {
    __nv_bfloat162 t = __floats2bfloat162_rn(a, b);
    return *(uint32_t*)&t;
}
__device__ __forceinline__ float bhi(float v) {
    return __bfloat162float(__float2bfloat16_rn(v));
}
__device__ __forceinline__ float swishf(float h) {
    return h * (1.f / (1.f + __expf(-h)));
}

// ---------------- kernel 1: batch stats (mean, rstd) --------------------
__global__ void stats_kernel(const float* __restrict__ x) {
    int tx = threadIdx.x & 31, ty = threadIdx.x >> 5;
    int c = blockIdx.x * 32 + tx;
    float s = 0.f, sq = 0.f;
    for (int r = ty; r < N_B; r += 8) {
        float v = x[r * D_K + c];
        s += v; sq += v * v;
    }
    __shared__ float ss[8][32], s2[8][32];
    ss[ty][tx] = s; s2[ty][tx] = sq;
    __syncthreads();
    if (ty == 0) {
        #pragma unroll
        for (int j = 1; j < 8; j++) { s += ss[j][tx]; sq += s2[j][tx]; }
        float mean = s * (1.f / N_B);
        float var  = sq * (1.f / N_B) - mean * mean;
        g_mean[c] = mean;
        g_rstd[c] = rsqrtf(var + 1e-5f);
    }
}

// ---------- kernel 2: normalize + split bf16 B images (swizzled) --------
__global__ void bconv_kernel(const float* __restrict__ x) {
    int id = blockIdx.x * 256 + threadIdx.x;   // 8192 threads
    int m  = id & 255;
    int ch = id >> 8;
    int kb = ch * KC;
    float v[32];
    #pragma unroll
    for (int q = 0; q < 8; q++) {
        float4 a  = *(const float4*)(x + m * D_K + kb + q * 4);
        float4 mu = *(const float4*)(g_mean + kb + q * 4);
        float4 rs = *(const float4*)(g_rstd + kb + q * 4);
        v[q * 4 + 0] = (a.x - mu.x) * rs.x;
        v[q * 4 + 1] = (a.y - mu.y) * rs.y;
        v[q * 4 + 2] = (a.z - mu.z) * rs.z;
        v[q * 4 + 3] = (a.w - mu.w) * rs.w;
    }
    uint4 un[8];
    #pragma unroll
    for (int u = 0; u < 4; u++) {          // hi units: k 8u..8u+7
        float h[8];
        #pragma unroll
        for (int j = 0; j < 8; j++) h[j] = bhi(v[u * 8 + j]);
        un[u] = make_uint4(pack2(h[0], h[1]), pack2(h[2], h[3]),
                           pack2(h[4], h[5]), pack2(h[6], h[7]));
        float l[8];
        #pragma unroll
        for (int j = 0; j < 8; j++) l[j] = v[u * 8 + j] - h[j];
        un[u + 4] = make_uint4(pack2(l[0], l[1]), pack2(l[2], l[3]),
                               pack2(l[4], l[5]), pack2(l[6], l[7]));
    }
    unsigned char* base = g_B + (size_t)ch * (N_B * 128) + m * 128;
    int rot = m & 7;
    #pragma unroll
    for (int u = 0; u < 8; u++)
        *(uint4*)(base + ((u ^ rot) << 4)) = un[u];
}

// ---------------- kernel 3: mma.sync bf16-split GEMM --------------------
// Zt[c][m] = swish( sum_k W[c][k] * B[m][k] + bias[c] )
__global__ __launch_bounds__(256) void mma_gemm(const float* __restrict__ W,
                                                const float* __restrict__ bias) {
    extern __shared__ char smem[];
    uint32_t sb = smem_u32(smem);
    int tid = threadIdx.x, lane = tid & 31, warp = tid >> 5;
    int c0 = blockIdx.x * TILE_C;
    int m0 = blockIdx.y * 128;
    int warp_c = warp & 1, warp_m = warp >> 1;

    // staging identity: thread -> (A row r, k-half)
    int r = tid >> 1, half = tid & 1;
    bool valid = (c0 + r) < C_DIM;
    const float* wsrc = W + (size_t)(c0 + r) * D_K + half * 16;
    uint32_t a_sts0 = (uint32_t)(r * 128 + half * 32);      // hi colb base
    const unsigned char* gB_m0 = g_B + (size_t)m0 * 128;

    // ldmatrix lane address components
    uint32_t a_row = (uint32_t)(warp_c * 64 + (lane & 7) + ((lane & 8) ? 8 : 0));
    uint32_t a_sel = (lane & 16) ? 16u : 0u;
    uint32_t b_row = (uint32_t)(warp_m * 32 + (lane & 7));
    uint32_t b_sel = (lane & 8) ? 16u : 0u;

    float acc[4][4][4];
    #pragma unroll
    for (int i = 0; i < 4; i++)
        #pragma unroll
        for (int j = 0; j < 4; j++)
            #pragma unroll
            for (int q = 0; q < 4; q++) acc[i][j][q] = 0.f;

    // ---- prologue: stage chunk 0 into buffer 0 ----
    {
        uint32_t Bb = sb + 16384;
        #pragma unroll
        for (int i = 0; i < 4; i++) {
            int u = tid + 256 * i;
            CP_ASYNC16(Bb + u * 16, gB_m0 + u * 16);
        }
        CP_COMMIT();
        char* smA = smem;
        #pragma unroll
        for (int j = 0; j < 4; j++) {
            float4 v = valid ? *(const float4*)(wsrc + j * 4)
                             : make_float4(0.f, 0.f, 0.f, 0.f);
            float hx = bhi(v.x), hy = bhi(v.y), hz = bhi(v.z), hw = bhi(v.w);
            uint32_t o = a_sts0 + j * 8;
            *(uint2*)(smA + SW128(o)) =
                make_uint2(pack2(hx, hy), pack2(hz, hw));
            *(uint2*)(smA + SW128(o + 64)) =
                make_uint2(pack2(v.x - hx, v.y - hy), pack2(v.z - hz, v.w - hw));
        }
        CP_WAIT0();
        __syncthreads();
    }

    for (int ch = 0; ch < NCH; ch++) {
        int nb = (ch + 1) & 1;
        bool has_next = (ch + 1) < NCH;
        float4 pre[4];
        if (has_next) {
            // B for next chunk via cp.async (prev readers of buffer nb done)
            uint32_t Bb = sb + nb * 32768 + 16384;
            const unsigned char* src =
                gB_m0 + (size_t)(ch + 1) * (N_B * 128);
            #pragma unroll
            for (int i = 0; i < 4; i++) {
                int u = tid + 256 * i;
                CP_ASYNC16(Bb + u * 16, src + u * 16);
            }
            CP_COMMIT();
            if (valid) {
                const float* s = wsrc + (ch + 1) * KC;
                #pragma unroll
                for (int j = 0; j < 4; j++) pre[j] = *(const float4*)(s + j * 4);
            } else {
                #pragma unroll
                for (int j = 0; j < 4; j++)
                    pre[j] = make_float4(0.f, 0.f, 0.f, 0.f);
            }
        }

        // ---- compute chunk ch from buffer ch&1 ----
        uint32_t Ab = sb + (ch & 1) * 32768;
        uint32_t Bb = Ab + 16384;
        #pragma unroll
        for (int s = 0; s < 2; s++) {
            uint32_t af[2][4][4], bf[2][4][2];
            #pragma unroll
            for (int p = 0; p < 2; p++)
                #pragma unroll
                for (int t = 0; t < 4; t++) {
                    uint32_t o = (a_row + t * 16) * 128 + s * 32 + p * 64 + a_sel;
                    LDSM4(af[p][t], Ab + SW128(o));
                }
            #pragma unroll
            for (int p = 0; p < 2; p++)
                #pragma unroll
                for (int t = 0; t < 4; t++) {
                    uint32_t o = (b_row + t * 8) * 128 + s * 32 + p * 64 + b_sel;
                    LDSM2(bf[p][t], Bb + SW128(o));
                }
            #pragma unroll
            for (int ct = 0; ct < 4; ct++)
                #pragma unroll
                for (int mt = 0; mt < 4; mt++) {
                    MMA16816(acc[ct][mt], af[0][ct], bf[0][mt]);
                    MMA16816(acc[ct][mt], af[0][ct], bf[1][mt]);
                    MMA16816(acc[ct][mt], af[1][ct], bf[0][mt]);
                }
        }

        if (has_next) {
            char* smA = smem + nb * 32768;
            #pragma unroll
            for (int j = 0; j < 4; j++) {
                float4 v = pre[j];
                float hx = bhi(v.x), hy = bhi(v.y), hz = bhi(v.z), hw = bhi(v.w);
                uint32_t o = a_sts0 + j * 8;
                *(uint2*)(smA + SW128(o)) =
                    make_uint2(pack2(hx, hy), pack2(hz, hw));
                *(uint2*)(smA + SW128(o + 64)) =
                    make_uint2(pack2(v.x - hx, v.y - hy), pack2(v.z - hz, v.w - hw));
            }
        }
        CP_WAIT0();
        __syncthreads();
    }

    // ---- epilogue: bias + swish -> Zt ----
    #pragma unroll
    for (int ct = 0; ct < 4; ct++) {
        int crow = c0 + warp_c * 64 + ct * 16 + (lane >> 2);
        float bv0 = (crow < C_DIM) ? __ldg(bias + crow) : 0.f;
        float bv1 = (crow + 8 < C_DIM) ? __ldg(bias + crow + 8) : 0.f;
        #pragma unroll
        for (int mt = 0; mt < 4; mt++) {
            int m = m0 + warp_m * 32 + mt * 8 + 2 * (lane & 3);
            float* d = acc[ct][mt];
            if (crow < C_DIM)
                *(float2*)(g_Zt + (size_t)crow * N_B + m) =
                    make_float2(swishf(d[0] + bv0), swishf(d[1] + bv0));
            if (crow + 8 < C_DIM)
                *(float2*)(g_Zt + (size_t)(crow + 8) * N_B + m) =
                    make_float2(swishf(d[2] + bv1), swishf(d[3] + bv1));
        }
    }
}

// ---------------- CSR build: zero, hist, scan x3, bucket-scatter --------
__global__ void zero_cnt_kernel() {
    int i = blockIdx.x * 256 + threadIdx.x;
    if (i < C_DIM) g_cnt[i] = 0;
}

__global__ void hist_kernel(const int* __restrict__ A_rows) {
    int e = blockIdx.x * 256 + threadIdx.x;
    if (e < E_TOT) atomicAdd(&g_cnt[A_rows[e]], 1);
}

__global__ void scan1_kernel() {
    int i = blockIdx.x * 256 + threadIdx.x;
    int v = (i < C_DIM) ? g_cnt[i] : 0;
    int lane = threadIdx.x & 31, w = threadIdx.x >> 5;
    int x = v;
    #pragma unroll
    for (int o = 1; o < 32; o <<= 1) {
        int y = __shfl_up_sync(~0u, x, o);
        if (lane >= o) x += y;
    }
    __shared__ int ws[8];
    if (lane == 31) ws[w] = x;
    __syncthreads();
    if (threadIdx.x < 8) {
        int s = ws[threadIdx.x];
        #pragma unroll
        for (int o = 1; o < 8; o <<= 1) {
            int y = __shfl_up_sync(0xff, s, o);
            if ((int)threadIdx.x >= o) s += y;
        }
        ws[threadIdx.x] = s;
    }
    __syncthreads();
    int off = (w > 0) ? ws[w - 1] : 0;
    int incl = x + off;
    if (i < C_DIM) g_local[i] = incl - v;
    if (threadIdx.x == 255) g_bsum[blockIdx.x] = incl;
}

__global__ void scan2_kernel() {
    int i = threadIdx.x;
    int v = (i < NBLK_SCAN) ? g_bsum[i] : 0;
    int lane = i & 31, w = i >> 5;
    int x = v;
    #pragma unroll
    for (int o = 1; o < 32; o <<= 1) {
        int y = __shfl_up_sync(~0u, x, o);
        if (lane >= o) x += y;
    }
    __shared__ int ws[8];
    if (lane == 31) ws[w] = x;
    __syncthreads();
    if (i < 8) {
        int s = ws[i];
        #pragma unroll
        for (int o = 1; o < 8; o <<= 1) {
            int y = __shfl_up_sync(0xff, s, o);
            if (i >= o) s += y;
        }
        ws[i] = s;
    }
    __syncthreads();
    int off = (w > 0) ? ws[w - 1] : 0;
    g_boff[i] = x + off - v;
}

__global__ void scan3_kernel() {
    int i = blockIdx.x * 256 + threadIdx.x;
    if (i < C_DIM) {
        int rs = g_local[i] + g_boff[i >> 8];
        g_rowstart[i] = rs;
        g_cursor[i]   = rs;
    }
    if (i == 0) g_rowstart[C_DIM] = E_TOT;
}

__global__ void build_kernel(const float* __restrict__ A_vals,
                             const float* __restrict__ vec,
                             const int* __restrict__ A_rows,
                             const int* __restrict__ A_cols) {
    int e = blockIdx.x * 256 + threadIdx.x;
    if (e >= E_TOT) return;
    int r = A_rows[e];
    int pos = atomicAdd(&g_cursor[r], 1);
    g_ecol[pos] = A_cols[e];
    g_ew[pos]   = A_vals[e] * __ldg(&vec[e / NNZ_G]);
}

// ---------------- SpMM: 64-thread group per row, register accumulate ----
__global__ __launch_bounds__(256) void spmm_kernel() {
    int row = blockIdx.x * 4 + (threadIdx.x >> 6);
    int t   = threadIdx.x & 63;
    if (row >= C_DIM) return;
    int beg = g_rowstart[row], end = g_rowstart[row + 1];
    const float4* Z4 = (const float4*)g_Zt;

    float4 acc = Z4[(size_t)row * 64 + t];       // residual Z init
    int e = beg;
    for (; e + 1 < end; e += 2) {
        int   c0 = g_ecol[e],     c1 = g_ecol[e + 1];
        float w0 = g_ew[e],       w1 = g_ew[e + 1];
        float4 v0 = Z4[(size_t)c0 * 64 + t];
        float4 v1 = Z4[(size_t)c1 * 64 + t];
        acc.x = fmaf(w0, v0.x, acc.x); acc.y = fmaf(w0, v0.y, acc.y);
        acc.z = fmaf(w0, v0.z, acc.z); acc.w = fmaf(w0, v0.w, acc.w);
        acc.x = fmaf(w1, v1.x, acc.x); acc.y = fmaf(w1, v1.y, acc.y);
        acc.z = fmaf(w1, v1.z, acc.z); acc.w = fmaf(w1, v1.w, acc.w);
    }
    if (e < end) {
        int   c0 = g_ecol[e];
        float w0 = g_ew[e];
        float4 v0 = Z4[(size_t)c0 * 64 + t];
        acc.x = fmaf(w0, v0.x, acc.x); acc.y = fmaf(w0, v0.y, acc.y);
        acc.z = fmaf(w0, v0.z, acc.z); acc.w = fmaf(w0, v0.w, acc.w);
    }
    ((float4*)g_NT)[(size_t)row * 64 + t] = acc;
}

// ---------------- transpose NT -> out [N, C] ----------------------------
__global__ void out_kernel(float* __restrict__ out) {
    __shared__ float tile[32][33];
    int c0 = blockIdx.x * 32, b0 = blockIdx.y * 32;
    int tx = threadIdx.x & 31, ty = threadIdx.x >> 5;
    for (int j = ty; j < 32; j += 8) {
        int c = c0 + j;
        tile[j][tx] = (c < C_DIM) ? g_NT[(size_t)c * N_B + b0 + tx] : 0.f;
    }
    __syncthreads();
    for (int j = ty; j < 32; j += 8) {
        int c = c0 + tx;
        if (c < C_DIM)
            out[(size_t)(b0 + j) * C_DIM + c] = tile[tx][j];
    }
}

// ---------------- launch ------------------------------------------------
extern "C" void kernel_launch(void* const* d_in, const int* in_sizes, int n_in,
                              void* d_out, int out_size) {
    const float* output = (const float*)d_in[0];
    const float* wt2_w  = (const float*)d_in[1];
    const float* wt2_b  = (const float*)d_in[2];
    const float* A_vals = (const float*)d_in[3];
    const float* vec    = (const float*)d_in[4];
    const int*   A_rows = (const int*)d_in[5];
    const int*   A_cols = (const int*)d_in[6];
    float* out = (float*)d_out;

    cudaFuncSetAttribute(mma_gemm, cudaFuncAttributeMaxDynamicSharedMemorySize,
                         GEMM_SMEM);

    int egrid = (E_TOT + 255) / 256;

    // CSR build (independent of GEMM chain)
    zero_cnt_kernel<<<NBLK_SCAN, 256>>>();
    hist_kernel<<<egrid, 256>>>(A_rows);
    scan1_kernel<<<NBLK_SCAN, 256>>>();
    scan2_kernel<<<1, 256>>>();
    scan3_kernel<<<NBLK_SCAN, 256>>>();
    build_kernel<<<egrid, 256>>>(A_vals, vec, A_rows, A_cols);

    // dense chain
    stats_kernel<<<D_K / 32, 256>>>(output);
    bconv_kernel<<<NCH, 256>>>(output);
    mma_gemm<<<dim3(NTILES, 2), 256, GEMM_SMEM>>>(wt2_w, wt2_b);

    // sparse aggregate + residual, then transpose out
    spmm_kernel<<<(C_DIM + 3) / 4, 256>>>();
    out_kernel<<<dim3((C_DIM + 31) / 32, N_B / 32), 256>>>(out);
}

// round 5
// speedup vs baseline: 3.2165x; 1.0886x over previous
#include <cuda_runtime.h>
#include <cuda_bf16.h>
#include <cstdint>

#define N_B   256
#define D_K   1024
#define C_DIM 50000
#define G_N   4
#define NNZ_G 300000
#define E_TOT (G_N * NNZ_G)
#define NBLK_SCAN ((C_DIM + 255) / 256)   // 196

#define KC    32
#define NCH   (D_K / KC)                  // 32
#define TILE_C 128
#define NTILES ((C_DIM + TILE_C - 1) / TILE_C)  // 391
#define GEMM_SMEM 65536                   // (A 16K + B 16K) x 2 stages

// ---------------- scratch (static __device__, no allocs) ----------------
__device__ float g_mean[D_K];
__device__ float g_rstd[D_K];
__device__ float g_Zt[(size_t)C_DIM * N_B]; // Z transposed:  [C, N]
__device__ float g_NT[(size_t)C_DIM * N_B]; // neighbors+Z transposed
// B images: per chunk, 256 m-rows of 128B = [hi k0..31 (64B) | lo (64B)], swizzled
__device__ unsigned char g_B[NCH * N_B * 128];

// CSR build scratch
__device__ int   g_cnt[C_DIM];
__device__ int   g_local[C_DIM];
__device__ int   g_bsum[256];
__device__ int   g_boff[256];
__device__ int   g_rowstart[C_DIM + 1];
__device__ int   g_cursor[C_DIM];
__device__ uint2 g_epack[E_TOT];           // (col, weight-bits)

// ---------------- helpers ----------------------------------------------
__device__ __forceinline__ uint32_t smem_u32(const void* p) {
    uint32_t a;
    asm("{ .reg .u64 t; cvta.to.shared.u64 t, %1; cvt.u32.u64 %0, t; }"
        : "=r"(a) : "l"(p));
    return a;
}
#define SW128(o) ((o) ^ (((o) >> 3) & 0x70))

#define LDSM4(f, addr) \
    asm volatile("ldmatrix.sync.aligned.m8n8.x4.shared.b16 {%0,%1,%2,%3}, [%4];" \
        : "=r"((f)[0]), "=r"((f)[1]), "=r"((f)[2]), "=r"((f)[3]) : "r"(addr))
#define LDSM2(f, addr) \
    asm volatile("ldmatrix.sync.aligned.m8n8.x2.shared.b16 {%0,%1}, [%2];" \
        : "=r"((f)[0]), "=r"((f)[1]) : "r"(addr))
#define MMA16816(d, a, b) \
    asm volatile("mma.sync.aligned.m16n8k16.row.col.f32.bf16.bf16.f32 " \
        "{%0,%1,%2,%3}, {%4,%5,%6,%7}, {%8,%9}, {%0,%1,%2,%3};" \
        : "+f"((d)[0]), "+f"((d)[1]), "+f"((d)[2]), "+f"((d)[3]) \
        : "r"((a)[0]), "r"((a)[1]), "r"((a)[2]), "r"((a)[3]), \
          "r"((b)[0]), "r"((b)[1]))
#define CP_ASYNC16(dst, src) \
    asm volatile("cp.async.cg.shared.global [%0], [%1], 16;" :: "r"(dst), "l"(src))
#define CP_COMMIT() asm volatile("cp.async.commit_group;" ::: "memory")
#define CP_WAIT0()  asm volatile("cp.async.wait_group 0;"  ::: "memory")

__device__ __forceinline__ uint32_t pack2(float a, float b) {
    __nv_bfloat162 t = __floats2bfloat162_rn(a, b);
    return *(uint32_t*)&t;
}
__device__ __forceinline__ float bhi(float v) {
    return __bfloat162float(__float2bfloat16_rn(v));
}
__device__ __forceinline__ float swishf(float h) {
    return h * (1.f / (1.f + __expf(-h)));
}

// ---------------- kernel 1: batch stats (mean, rstd) --------------------
__global__ void stats_kernel(const float* __restrict__ x) {
    int tx = threadIdx.x & 31, ty = threadIdx.x >> 5;
    int c = blockIdx.x * 32 + tx;
    float s = 0.f, sq = 0.f;
    for (int r = ty; r < N_B; r += 8) {
        float v = x[r * D_K + c];
        s += v; sq += v * v;
    }
    __shared__ float ss[8][32], s2[8][32];
    ss[ty][tx] = s; s2[ty][tx] = sq;
    __syncthreads();
    if (ty == 0) {
        #pragma unroll
        for (int j = 1; j < 8; j++) { s += ss[j][tx]; sq += s2[j][tx]; }
        float mean = s * (1.f / N_B);
        float var  = sq * (1.f / N_B) - mean * mean;
        g_mean[c] = mean;
        g_rstd[c] = rsqrtf(var + 1e-5f);
    }
}

// ---------- kernel 2: normalize + split bf16 B images (swizzled) --------
__global__ void bconv_kernel(const float* __restrict__ x) {
    int id = blockIdx.x * 256 + threadIdx.x;   // 8192 threads
    int m  = id & 255;
    int ch = id >> 8;
    int kb = ch * KC;
    float v[32];
    #pragma unroll
    for (int q = 0; q < 8; q++) {
        float4 a  = *(const float4*)(x + m * D_K + kb + q * 4);
        float4 mu = *(const float4*)(g_mean + kb + q * 4);
        float4 rs = *(const float4*)(g_rstd + kb + q * 4);
        v[q * 4 + 0] = (a.x - mu.x) * rs.x;
        v[q * 4 + 1] = (a.y - mu.y) * rs.y;
        v[q * 4 + 2] = (a.z - mu.z) * rs.z;
        v[q * 4 + 3] = (a.w - mu.w) * rs.w;
    }
    uint4 un[8];
    #pragma unroll
    for (int u = 0; u < 4; u++) {
        float h[8];
        #pragma unroll
        for (int j = 0; j < 8; j++) h[j] = bhi(v[u * 8 + j]);
        un[u] = make_uint4(pack2(h[0], h[1]), pack2(h[2], h[3]),
                           pack2(h[4], h[5]), pack2(h[6], h[7]));
        float l[8];
        #pragma unroll
        for (int j = 0; j < 8; j++) l[j] = v[u * 8 + j] - h[j];
        un[u + 4] = make_uint4(pack2(l[0], l[1]), pack2(l[2], l[3]),
                               pack2(l[4], l[5]), pack2(l[6], l[7]));
    }
    unsigned char* base = g_B + (size_t)ch * (N_B * 128) + m * 128;
    int rot = m & 7;
    #pragma unroll
    for (int u = 0; u < 8; u++)
        *(uint4*)(base + ((u ^ rot) << 4)) = un[u];
}

// ---------------- kernel 3: mma.sync bf16-split GEMM (one m-half) -------
__global__ __launch_bounds__(256) void mma_gemm(const float* __restrict__ W,
                                                const float* __restrict__ bias,
                                                int m0) {
    extern __shared__ char smem[];
    uint32_t sb = smem_u32(smem);
    int tid = threadIdx.x, lane = tid & 31, warp = tid >> 5;
    int c0 = blockIdx.x * TILE_C;
    int warp_c = warp & 1, warp_m = warp >> 1;

    int r = tid >> 1, half = tid & 1;
    bool valid = (c0 + r) < C_DIM;
    const float* wsrc = W + (size_t)(c0 + r) * D_K + half * 16;
    uint32_t a_sts0 = (uint32_t)(r * 128 + half * 32);
    const unsigned char* gB_m0 = g_B + (size_t)m0 * 128;

    uint32_t a_row = (uint32_t)(warp_c * 64 + (lane & 7) + ((lane & 8) ? 8 : 0));
    uint32_t a_sel = (lane & 16) ? 16u : 0u;
    uint32_t b_row = (uint32_t)(warp_m * 32 + (lane & 7));
    uint32_t b_sel = (lane & 8) ? 16u : 0u;

    float acc[4][4][4];
    #pragma unroll
    for (int i = 0; i < 4; i++)
        #pragma unroll
        for (int j = 0; j < 4; j++)
            #pragma unroll
            for (int q = 0; q < 4; q++) acc[i][j][q] = 0.f;

    {
        uint32_t Bb = sb + 16384;
        #pragma unroll
        for (int i = 0; i < 4; i++) {
            int u = tid + 256 * i;
            CP_ASYNC16(Bb + u * 16, gB_m0 + u * 16);
        }
        CP_COMMIT();
        char* smA = smem;
        #pragma unroll
        for (int j = 0; j < 4; j++) {
            float4 v = valid ? *(const float4*)(wsrc + j * 4)
                             : make_float4(0.f, 0.f, 0.f, 0.f);
            float hx = bhi(v.x), hy = bhi(v.y), hz = bhi(v.z), hw = bhi(v.w);
            uint32_t o = a_sts0 + j * 8;
            *(uint2*)(smA + SW128(o)) =
                make_uint2(pack2(hx, hy), pack2(hz, hw));
            *(uint2*)(smA + SW128(o + 64)) =
                make_uint2(pack2(v.x - hx, v.y - hy), pack2(v.z - hz, v.w - hw));
        }
        CP_WAIT0();
        __syncthreads();
    }

    for (int ch = 0; ch < NCH; ch++) {
        int nb = (ch + 1) & 1;
        bool has_next = (ch + 1) < NCH;
        float4 pre[4];
        if (has_next) {
            uint32_t Bb = sb + nb * 32768 + 16384;
            const unsigned char* src =
                gB_m0 + (size_t)(ch + 1) * (N_B * 128);
            #pragma unroll
            for (int i = 0; i < 4; i++) {
                int u = tid + 256 * i;
                CP_ASYNC16(Bb + u * 16, src + u * 16);
            }
            CP_COMMIT();
            if (valid) {
                const float* s = wsrc + (ch + 1) * KC;
                #pragma unroll
                for (int j = 0; j < 4; j++) pre[j] = *(const float4*)(s + j * 4);
            } else {
                #pragma unroll
                for (int j = 0; j < 4; j++)
                    pre[j] = make_float4(0.f, 0.f, 0.f, 0.f);
            }
        }

        uint32_t Ab = sb + (ch & 1) * 32768;
        uint32_t Bb = Ab + 16384;
        #pragma unroll
        for (int s = 0; s < 2; s++) {
            uint32_t af[2][4][4], bf[2][4][2];
            #pragma unroll
            for (int p = 0; p < 2; p++)
                #pragma unroll
                for (int t = 0; t < 4; t++) {
                    uint32_t o = (a_row + t * 16) * 128 + s * 32 + p * 64 + a_sel;
                    LDSM4(af[p][t], Ab + SW128(o));
                }
            #pragma unroll
            for (int p = 0; p < 2; p++)
                #pragma unroll
                for (int t = 0; t < 4; t++) {
                    uint32_t o = (b_row + t * 8) * 128 + s * 32 + p * 64 + b_sel;
                    LDSM2(bf[p][t], Bb + SW128(o));
                }
            #pragma unroll
            for (int ct = 0; ct < 4; ct++)
                #pragma unroll
                for (int mt = 0; mt < 4; mt++) {
                    MMA16816(acc[ct][mt], af[0][ct], bf[0][mt]);
                    MMA16816(acc[ct][mt], af[0][ct], bf[1][mt]);
                    MMA16816(acc[ct][mt], af[1][ct], bf[0][mt]);
                }
        }

        if (has_next) {
            char* smA = smem + nb * 32768;
            #pragma unroll
            for (int j = 0; j < 4; j++) {
                float4 v = pre[j];
                float hx = bhi(v.x), hy = bhi(v.y), hz = bhi(v.z), hw = bhi(v.w);
                uint32_t o = a_sts0 + j * 8;
                *(uint2*)(smA + SW128(o)) =
                    make_uint2(pack2(hx, hy), pack2(hz, hw));
                *(uint2*)(smA + SW128(o + 64)) =
                    make_uint2(pack2(v.x - hx, v.y - hy), pack2(v.z - hz, v.w - hw));
            }
        }
        CP_WAIT0();
        __syncthreads();
    }

    #pragma unroll
    for (int ct = 0; ct < 4; ct++) {
        int crow = c0 + warp_c * 64 + ct * 16 + (lane >> 2);
        float bv0 = (crow < C_DIM) ? __ldg(bias + crow) : 0.f;
        float bv1 = (crow + 8 < C_DIM) ? __ldg(bias + crow + 8) : 0.f;
        #pragma unroll
        for (int mt = 0; mt < 4; mt++) {
            int m = m0 + warp_m * 32 + mt * 8 + 2 * (lane & 3);
            float* d = acc[ct][mt];
            if (crow < C_DIM)
                *(float2*)(g_Zt + (size_t)crow * N_B + m) =
                    make_float2(swishf(d[0] + bv0), swishf(d[1] + bv0));
            if (crow + 8 < C_DIM)
                *(float2*)(g_Zt + (size_t)(crow + 8) * N_B + m) =
                    make_float2(swishf(d[2] + bv1), swishf(d[3] + bv1));
        }
    }
}

// ---------------- CSR build: zero, hist, scan x3, bucket-scatter --------
__global__ void zero_cnt_kernel() {
    int i = blockIdx.x * 256 + threadIdx.x;
    if (i < C_DIM) g_cnt[i] = 0;
}

__global__ void hist_kernel(const int* __restrict__ A_rows) {
    int e = blockIdx.x * 256 + threadIdx.x;
    if (e < E_TOT) atomicAdd(&g_cnt[A_rows[e]], 1);
}

__global__ void scan1_kernel() {
    int i = blockIdx.x * 256 + threadIdx.x;
    int v = (i < C_DIM) ? g_cnt[i] : 0;
    int lane = threadIdx.x & 31, w = threadIdx.x >> 5;
    int x = v;
    #pragma unroll
    for (int o = 1; o < 32; o <<= 1) {
        int y = __shfl_up_sync(~0u, x, o);
        if (lane >= o) x += y;
    }
    __shared__ int ws[8];
    if (lane == 31) ws[w] = x;
    __syncthreads();
    if (threadIdx.x < 8) {
        int s = ws[threadIdx.x];
        #pragma unroll
        for (int o = 1; o < 8; o <<= 1) {
            int y = __shfl_up_sync(0xff, s, o);
            if ((int)threadIdx.x >= o) s += y;
        }
        ws[threadIdx.x] = s;
    }
    __syncthreads();
    int off = (w > 0) ? ws[w - 1] : 0;
    int incl = x + off;
    if (i < C_DIM) g_local[i] = incl - v;
    if (threadIdx.x == 255) g_bsum[blockIdx.x] = incl;
}

__global__ void scan2_kernel() {
    int i = threadIdx.x;
    int v = (i < NBLK_SCAN) ? g_bsum[i] : 0;
    int lane = i & 31, w = i >> 5;
    int x = v;
    #pragma unroll
    for (int o = 1; o < 32; o <<= 1) {
        int y = __shfl_up_sync(~0u, x, o);
        if (lane >= o) x += y;
    }
    __shared__ int ws[8];
    if (lane == 31) ws[w] = x;
    __syncthreads();
    if (i < 8) {
        int s = ws[i];
        #pragma unroll
        for (int o = 1; o < 8; o <<= 1) {
            int y = __shfl_up_sync(0xff, s, o);
            if (i >= o) s += y;
        }
        ws[i] = s;
    }
    __syncthreads();
    int off = (w > 0) ? ws[w - 1] : 0;
    g_boff[i] = x + off - v;
}

__global__ void scan3_kernel() {
    int i = blockIdx.x * 256 + threadIdx.x;
    if (i < C_DIM) {
        int rs = g_local[i] + g_boff[i >> 8];
        g_rowstart[i] = rs;
        g_cursor[i]   = rs;
    }
    if (i == 0) g_rowstart[C_DIM] = E_TOT;
}

__global__ void build_kernel(const float* __restrict__ A_vals,
                             const float* __restrict__ vec,
                             const int* __restrict__ A_rows,
                             const int* __restrict__ A_cols) {
    int e = blockIdx.x * 256 + threadIdx.x;
    if (e >= E_TOT) return;
    int r = A_rows[e];
    int pos = atomicAdd(&g_cursor[r], 1);
    g_epack[pos] = make_uint2((uint32_t)A_cols[e],
                              __float_as_uint(A_vals[e] * __ldg(&vec[e / NNZ_G])));
}

// -------- SpMM (one n-half): warp per row, 4-edge unrolled gather -------
__global__ __launch_bounds__(256) void spmm_kernel(int nhalf) {
    int row = blockIdx.x * 8 + (threadIdx.x >> 5);
    if (row >= C_DIM) return;
    int t = (threadIdx.x & 31) | (nhalf << 5);   // float4 lane in [0,64)
    int beg = g_rowstart[row], end = g_rowstart[row + 1];
    const float4* Z4 = (const float4*)g_Zt;
    const uint2* E = g_epack;

    float4 acc = Z4[(size_t)row * 64 + t];       // residual Z init
    int e = beg;
    for (; e + 4 <= end; e += 4) {
        uint2 p0 = E[e], p1 = E[e + 1], p2 = E[e + 2], p3 = E[e + 3];
        float4 v0 = Z4[(size_t)p0.x * 64 + t];
        float4 v1 = Z4[(size_t)p1.x * 64 + t];
        float4 v2 = Z4[(size_t)p2.x * 64 + t];
        float4 v3 = Z4[(size_t)p3.x * 64 + t];
        float w0 = __uint_as_float(p0.y), w1 = __uint_as_float(p1.y);
        float w2 = __uint_as_float(p2.y), w3 = __uint_as_float(p3.y);
        acc.x = fmaf(w0, v0.x, acc.x); acc.y = fmaf(w0, v0.y, acc.y);
        acc.z = fmaf(w0, v0.z, acc.z); acc.w = fmaf(w0, v0.w, acc.w);
        acc.x = fmaf(w1, v1.x, acc.x); acc.y = fmaf(w1, v1.y, acc.y);
        acc.z = fmaf(w1, v1.z, acc.z); acc.w = fmaf(w1, v1.w, acc.w);
        acc.x = fmaf(w2, v2.x, acc.x); acc.y = fmaf(w2, v2.y, acc.y);
        acc.z = fmaf(w2, v2.z, acc.z); acc.w = fmaf(w2, v2.w, acc.w);
        acc.x = fmaf(w3, v3.x, acc.x); acc.y = fmaf(w3, v3.y, acc.y);
        acc.z = fmaf(w3, v3.z, acc.z); acc.w = fmaf(w3, v3.w, acc.w);
    }
    for (; e < end; e++) {
        uint2 p = E[e];
        float w = __uint_as_float(p.y);
        float4 v = Z4[(size_t)p.x * 64 + t];
        acc.x = fmaf(w, v.x, acc.x); acc.y = fmaf(w, v.y, acc.y);
        acc.z = fmaf(w, v.z, acc.z); acc.w = fmaf(w, v.w, acc.w);
    }
    ((float4*)g_NT)[(size_t)row * 64 + t] = acc;
}

// -------- transpose NT -> out [N, C] (one n-half) -----------------------
__global__ void out_kernel(float* __restrict__ out, int nhalf) {
    __shared__ float tile[32][33];
    int c0 = blockIdx.x * 32, b0 = nhalf * 128 + blockIdx.y * 32;
    int tx = threadIdx.x & 31, ty = threadIdx.x >> 5;
    for (int j = ty; j < 32; j += 8) {
        int c = c0 + j;
        tile[j][tx] = (c < C_DIM) ? g_NT[(size_t)c * N_B + b0 + tx] : 0.f;
    }
    __syncthreads();
    for (int j = ty; j < 32; j += 8) {
        int c = c0 + tx;
        if (c < C_DIM)
            out[(size_t)(b0 + j) * C_DIM + c] = tile[tx][j];
    }
}

// ---------------- launch: forked-stream pipeline ------------------------
extern "C" void kernel_launch(void* const* d_in, const int* in_sizes, int n_in,
                              void* d_out, int out_size) {
    const float* output = (const float*)d_in[0];
    const float* wt2_w  = (const float*)d_in[1];
    const float* wt2_b  = (const float*)d_in[2];
    const float* A_vals = (const float*)d_in[3];
    const float* vec    = (const float*)d_in[4];
    const int*   A_rows = (const int*)d_in[5];
    const int*   A_cols = (const int*)d_in[6];
    float* out = (float*)d_out;

    static cudaStream_t sCsr = nullptr, sAux = nullptr;
    static cudaEvent_t evFork = nullptr, evCsr = nullptr, evGemmA = nullptr,
                       evAux = nullptr;
    if (!sCsr) {
        cudaStreamCreateWithFlags(&sCsr, cudaStreamNonBlocking);
        cudaStreamCreateWithFlags(&sAux, cudaStreamNonBlocking);
        cudaEventCreateWithFlags(&evFork, cudaEventDisableTiming);
        cudaEventCreateWithFlags(&evCsr, cudaEventDisableTiming);
        cudaEventCreateWithFlags(&evGemmA, cudaEventDisableTiming);
        cudaEventCreateWithFlags(&evAux, cudaEventDisableTiming);
        cudaFuncSetAttribute(mma_gemm,
                             cudaFuncAttributeMaxDynamicSharedMemorySize,
                             GEMM_SMEM);
    }

    int egrid = (E_TOT + 255) / 256;

    // fork
    cudaEventRecord(evFork, 0);
    cudaStreamWaitEvent(sCsr, evFork, 0);
    cudaStreamWaitEvent(sAux, evFork, 0);

    // CSR build on its own stream (independent of dense chain)
    zero_cnt_kernel<<<NBLK_SCAN, 256, 0, sCsr>>>();
    hist_kernel<<<egrid, 256, 0, sCsr>>>(A_rows);
    scan1_kernel<<<NBLK_SCAN, 256, 0, sCsr>>>();
    scan2_kernel<<<1, 256, 0, sCsr>>>();
    scan3_kernel<<<NBLK_SCAN, 256, 0, sCsr>>>();
    build_kernel<<<egrid, 256, 0, sCsr>>>(A_vals, vec, A_rows, A_cols);
    cudaEventRecord(evCsr, sCsr);

    // dense chain on main stream
    stats_kernel<<<D_K / 32, 256>>>(output);
    bconv_kernel<<<NCH, 256>>>(output);
    mma_gemm<<<NTILES, 256, GEMM_SMEM>>>(wt2_w, wt2_b, 0);      // n-half 0
    cudaEventRecord(evGemmA, 0);
    mma_gemm<<<NTILES, 256, GEMM_SMEM>>>(wt2_w, wt2_b, 128);    // n-half 1

    // aux stream: half-0 spmm + transpose, overlapped with gemm half-1
    cudaStreamWaitEvent(sAux, evGemmA, 0);
    cudaStreamWaitEvent(sAux, evCsr, 0);
    spmm_kernel<<<(C_DIM + 7) / 8, 256, 0, sAux>>>(0);
    out_kernel<<<dim3((C_DIM + 31) / 32, 4), 256, 0, sAux>>>(out, 0);
    cudaEventRecord(evAux, sAux);

    // main stream: half-1 spmm + transpose after gemm half-1
    cudaStreamWaitEvent(0, evCsr, 0);
    spmm_kernel<<<(C_DIM + 7) / 8, 256>>>(1);
    out_kernel<<<dim3((C_DIM + 31) / 32, 4), 256>>>(out, 1);

    // join
    cudaStreamWaitEvent(0, evAux, 0);
}

// round 6
// speedup vs baseline: 3.2819x; 1.0203x over previous
#include <cuda_runtime.h>
#include <cuda_bf16.h>
#include <cuda_fp16.h>
#include <cstdint>

#define N_B   256
#define D_K   1024
#define C_DIM 50000
#define G_N   4
#define NNZ_G 300000
#define E_TOT (G_N * NNZ_G)
#define NBLK_SCAN ((C_DIM + 255) / 256)   // 196

#define KC    32
#define NCH   (D_K / KC)                  // 32
#define TILE_C 128
#define NTILES ((C_DIM + TILE_C - 1) / TILE_C)  // 391
#define GEMM_SMEM 65536                   // (A 16K + B 16K) x 2 stages

// ---------------- scratch (static __device__, no allocs) ----------------
__device__ float g_mean[D_K];
__device__ float g_rstd[D_K];
__device__ float g_Zt[(size_t)C_DIM * N_B]; // Z transposed (fp32, residual)
__device__ __half g_Zh[(size_t)C_DIM * N_B]; // Z transposed (fp16, gather img)
__device__ float g_NT[(size_t)C_DIM * N_B]; // neighbors+Z transposed
// B images: per chunk, 256 m-rows of 128B = [hi (64B) | lo (64B)], swizzled
__device__ unsigned char g_B[NCH * N_B * 128];

// CSR build scratch
__device__ int   g_cnt[C_DIM];
__device__ int   g_local[C_DIM];
__device__ int   g_bsum[256];
__device__ int   g_boff[256];
__device__ int   g_rowstart[C_DIM + 1];
__device__ int   g_cursor[C_DIM];
__device__ uint2 g_epack[E_TOT];           // (col, weight-bits)

// ---------------- helpers ----------------------------------------------
__device__ __forceinline__ uint32_t smem_u32(const void* p) {
    uint32_t a;
    asm("{ .reg .u64 t; cvta.to.shared.u64 t, %1; cvt.u32.u64 %0, t; }"
        : "=r"(a) : "l"(p));
    return a;
}
#define SW128(o) ((o) ^ (((o) >> 3) & 0x70))

#define LDSM4(f, addr) \
    asm volatile("ldmatrix.sync.aligned.m8n8.x4.shared.b16 {%0,%1,%2,%3}, [%4];" \
        : "=r"((f)[0]), "=r"((f)[1]), "=r"((f)[2]), "=r"((f)[3]) : "r"(addr))
#define LDSM2(f, addr) \
    asm volatile("ldmatrix.sync.aligned.m8n8.x2.shared.b16 {%0,%1}, [%2];" \
        : "=r"((f)[0]), "=r"((f)[1]) : "r"(addr))
#define MMA16816(d, a, b) \
    asm volatile("mma.sync.aligned.m16n8k16.row.col.f32.bf16.bf16.f32 " \
        "{%0,%1,%2,%3}, {%4,%5,%6,%7}, {%8,%9}, {%0,%1,%2,%3};" \
        : "+f"((d)[0]), "+f"((d)[1]), "+f"((d)[2]), "+f"((d)[3]) \
        : "r"((a)[0]), "r"((a)[1]), "r"((a)[2]), "r"((a)[3]), \
          "r"((b)[0]), "r"((b)[1]))
#define CP_ASYNC16(dst, src) \
    asm volatile("cp.async.cg.shared.global [%0], [%1], 16;" :: "r"(dst), "l"(src))
#define CP_COMMIT() asm volatile("cp.async.commit_group;" ::: "memory")
#define CP_WAIT0()  asm volatile("cp.async.wait_group 0;"  ::: "memory")

__device__ __forceinline__ uint32_t pack2(float a, float b) {
    __nv_bfloat162 t = __floats2bfloat162_rn(a, b);
    return *(uint32_t*)&t;
}
__device__ __forceinline__ float bhi(float v) {
    return __bfloat162float(__float2bfloat16_rn(v));
}
__device__ __forceinline__ float swishf(float h) {
    return h * (1.f / (1.f + __expf(-h)));
}

// ---------------- kernel 1: batch stats (mean, rstd) --------------------
__global__ void stats_kernel(const float* __restrict__ x) {
    int tx = threadIdx.x & 31, ty = threadIdx.x >> 5;
    int c = blockIdx.x * 32 + tx;
    float s = 0.f, sq = 0.f;
    for (int r = ty; r < N_B; r += 8) {
        float v = x[r * D_K + c];
        s += v; sq += v * v;
    }
    __shared__ float ss[8][32], s2[8][32];
    ss[ty][tx] = s; s2[ty][tx] = sq;
    __syncthreads();
    if (ty == 0) {
        #pragma unroll
        for (int j = 1; j < 8; j++) { s += ss[j][tx]; sq += s2[j][tx]; }
        float mean = s * (1.f / N_B);
        float var  = sq * (1.f / N_B) - mean * mean;
        g_mean[c] = mean;
        g_rstd[c] = rsqrtf(var + 1e-5f);
    }
}

// ---------- kernel 2: normalize + split bf16 B images (swizzled) --------
__global__ void bconv_kernel(const float* __restrict__ x) {
    int id = blockIdx.x * 256 + threadIdx.x;   // 8192 threads
    int m  = id & 255;
    int ch = id >> 8;
    int kb = ch * KC;
    float v[32];
    #pragma unroll
    for (int q = 0; q < 8; q++) {
        float4 a  = *(const float4*)(x + m * D_K + kb + q * 4);
        float4 mu = *(const float4*)(g_mean + kb + q * 4);
        float4 rs = *(const float4*)(g_rstd + kb + q * 4);
        v[q * 4 + 0] = (a.x - mu.x) * rs.x;
        v[q * 4 + 1] = (a.y - mu.y) * rs.y;
        v[q * 4 + 2] = (a.z - mu.z) * rs.z;
        v[q * 4 + 3] = (a.w - mu.w) * rs.w;
    }
    uint4 un[8];
    #pragma unroll
    for (int u = 0; u < 4; u++) {
        float h[8];
        #pragma unroll
        for (int j = 0; j < 8; j++) h[j] = bhi(v[u * 8 + j]);
        un[u] = make_uint4(pack2(h[0], h[1]), pack2(h[2], h[3]),
                           pack2(h[4], h[5]), pack2(h[6], h[7]));
        float l[8];
        #pragma unroll
        for (int j = 0; j < 8; j++) l[j] = v[u * 8 + j] - h[j];
        un[u + 4] = make_uint4(pack2(l[0], l[1]), pack2(l[2], l[3]),
                               pack2(l[4], l[5]), pack2(l[6], l[7]));
    }
    unsigned char* base = g_B + (size_t)ch * (N_B * 128) + m * 128;
    int rot = m & 7;
    #pragma unroll
    for (int u = 0; u < 8; u++)
        *(uint4*)(base + ((u ^ rot) << 4)) = un[u];
}

// ---------------- kernel 3: mma.sync bf16-split GEMM (one m-half) -------
__global__ __launch_bounds__(256) void mma_gemm(const float* __restrict__ W,
                                                const float* __restrict__ bias,
                                                int m0) {
    extern __shared__ char smem[];
    uint32_t sb = smem_u32(smem);
    int tid = threadIdx.x, lane = tid & 31, warp = tid >> 5;
    int c0 = blockIdx.x * TILE_C;
    int warp_c = warp & 1, warp_m = warp >> 1;

    int r = tid >> 1, half = tid & 1;
    bool valid = (c0 + r) < C_DIM;
    const float* wsrc = W + (size_t)(c0 + r) * D_K + half * 16;
    uint32_t a_sts0 = (uint32_t)(r * 128 + half * 32);
    const unsigned char* gB_m0 = g_B + (size_t)m0 * 128;

    uint32_t a_row = (uint32_t)(warp_c * 64 + (lane & 7) + ((lane & 8) ? 8 : 0));
    uint32_t a_sel = (lane & 16) ? 16u : 0u;
    uint32_t b_row = (uint32_t)(warp_m * 32 + (lane & 7));
    uint32_t b_sel = (lane & 8) ? 16u : 0u;

    float acc[4][4][4];
    #pragma unroll
    for (int i = 0; i < 4; i++)
        #pragma unroll
        for (int j = 0; j < 4; j++)
            #pragma unroll
            for (int q = 0; q < 4; q++) acc[i][j][q] = 0.f;

    {
        uint32_t Bb = sb + 16384;
        #pragma unroll
        for (int i = 0; i < 4; i++) {
            int u = tid + 256 * i;
            CP_ASYNC16(Bb + u * 16, gB_m0 + u * 16);
        }
        CP_COMMIT();
        char* smA = smem;
        #pragma unroll
        for (int j = 0; j < 4; j++) {
            float4 v = valid ? *(const float4*)(wsrc + j * 4)
                             : make_float4(0.f, 0.f, 0.f, 0.f);
            float hx = bhi(v.x), hy = bhi(v.y), hz = bhi(v.z), hw = bhi(v.w);
            uint32_t o = a_sts0 + j * 8;
            *(uint2*)(smA + SW128(o)) =
                make_uint2(pack2(hx, hy), pack2(hz, hw));
            *(uint2*)(smA + SW128(o + 64)) =
                make_uint2(pack2(v.x - hx, v.y - hy), pack2(v.z - hz, v.w - hw));
        }
        CP_WAIT0();
        __syncthreads();
    }

    for (int ch = 0; ch < NCH; ch++) {
        int nb = (ch + 1) & 1;
        bool has_next = (ch + 1) < NCH;
        float4 pre[4];
        if (has_next) {
            uint32_t Bb = sb + nb * 32768 + 16384;
            const unsigned char* src =
                gB_m0 + (size_t)(ch + 1) * (N_B * 128);
            #pragma unroll
            for (int i = 0; i < 4; i++) {
                int u = tid + 256 * i;
                CP_ASYNC16(Bb + u * 16, src + u * 16);
            }
            CP_COMMIT();
            if (valid) {
                const float* s = wsrc + (ch + 1) * KC;
                #pragma unroll
                for (int j = 0; j < 4; j++) pre[j] = *(const float4*)(s + j * 4);
            } else {
                #pragma unroll
                for (int j = 0; j < 4; j++)
                    pre[j] = make_float4(0.f, 0.f, 0.f, 0.f);
            }
        }

        uint32_t Ab = sb + (ch & 1) * 32768;
        uint32_t Bb = Ab + 16384;
        #pragma unroll
        for (int s = 0; s < 2; s++) {
            uint32_t af[2][4][4], bf[2][4][2];
            #pragma unroll
            for (int p = 0; p < 2; p++)
                #pragma unroll
                for (int t = 0; t < 4; t++) {
                    uint32_t o = (a_row + t * 16) * 128 + s * 32 + p * 64 + a_sel;
                    LDSM4(af[p][t], Ab + SW128(o));
                }
            #pragma unroll
            for (int p = 0; p < 2; p++)
                #pragma unroll
                for (int t = 0; t < 4; t++) {
                    uint32_t o = (b_row + t * 8) * 128 + s * 32 + p * 64 + b_sel;
                    LDSM2(bf[p][t], Bb + SW128(o));
                }
            #pragma unroll
            for (int ct = 0; ct < 4; ct++)
                #pragma unroll
                for (int mt = 0; mt < 4; mt++) {
                    MMA16816(acc[ct][mt], af[0][ct], bf[0][mt]);
                    MMA16816(acc[ct][mt], af[0][ct], bf[1][mt]);
                    MMA16816(acc[ct][mt], af[1][ct], bf[0][mt]);
                }
        }

        if (has_next) {
            char* smA = smem + nb * 32768;
            #pragma unroll
            for (int j = 0; j < 4; j++) {
                float4 v = pre[j];
                float hx = bhi(v.x), hy = bhi(v.y), hz = bhi(v.z), hw = bhi(v.w);
                uint32_t o = a_sts0 + j * 8;
                *(uint2*)(smA + SW128(o)) =
                    make_uint2(pack2(hx, hy), pack2(hz, hw));
                *(uint2*)(smA + SW128(o + 64)) =
                    make_uint2(pack2(v.x - hx, v.y - hy), pack2(v.z - hz, v.w - hw));
            }
        }
        CP_WAIT0();
        __syncthreads();
    }

    #pragma unroll
    for (int ct = 0; ct < 4; ct++) {
        int crow = c0 + warp_c * 64 + ct * 16 + (lane >> 2);
        float bv0 = (crow < C_DIM) ? __ldg(bias + crow) : 0.f;
        float bv1 = (crow + 8 < C_DIM) ? __ldg(bias + crow + 8) : 0.f;
        #pragma unroll
        for (int mt = 0; mt < 4; mt++) {
            int m = m0 + warp_m * 32 + mt * 8 + 2 * (lane & 3);
            float* d = acc[ct][mt];
            if (crow < C_DIM) {
                float z0 = swishf(d[0] + bv0), z1 = swishf(d[1] + bv0);
                *(float2*)(g_Zt + (size_t)crow * N_B + m) = make_float2(z0, z1);
                *(__half2*)(g_Zh + (size_t)crow * N_B + m) =
                    __floats2half2_rn(z0, z1);
            }
            if (crow + 8 < C_DIM) {
                float z2 = swishf(d[2] + bv1), z3 = swishf(d[3] + bv1);
                *(float2*)(g_Zt + (size_t)(crow + 8) * N_B + m) =
                    make_float2(z2, z3);
                *(__half2*)(g_Zh + (size_t)(crow + 8) * N_B + m) =
                    __floats2half2_rn(z2, z3);
            }
        }
    }
}

// ---------------- CSR build: zero, hist, scan x3, bucket-scatter --------
__global__ void zero_cnt_kernel() {
    int i = blockIdx.x * 256 + threadIdx.x;
    if (i < C_DIM) g_cnt[i] = 0;
}

__global__ void hist_kernel(const int* __restrict__ A_rows) {
    int e = blockIdx.x * 256 + threadIdx.x;
    if (e < E_TOT) atomicAdd(&g_cnt[A_rows[e]], 1);
}

__global__ void scan1_kernel() {
    int i = blockIdx.x * 256 + threadIdx.x;
    int v = (i < C_DIM) ? g_cnt[i] : 0;
    int lane = threadIdx.x & 31, w = threadIdx.x >> 5;
    int x = v;
    #pragma unroll
    for (int o = 1; o < 32; o <<= 1) {
        int y = __shfl_up_sync(~0u, x, o);
        if (lane >= o) x += y;
    }
    __shared__ int ws[8];
    if (lane == 31) ws[w] = x;
    __syncthreads();
    if (threadIdx.x < 8) {
        int s = ws[threadIdx.x];
        #pragma unroll
        for (int o = 1; o < 8; o <<= 1) {
            int y = __shfl_up_sync(0xff, s, o);
            if ((int)threadIdx.x >= o) s += y;
        }
        ws[threadIdx.x] = s;
    }
    __syncthreads();
    int off = (w > 0) ? ws[w - 1] : 0;
    int incl = x + off;
    if (i < C_DIM) g_local[i] = incl - v;
    if (threadIdx.x == 255) g_bsum[blockIdx.x] = incl;
}

__global__ void scan2_kernel() {
    int i = threadIdx.x;
    int v = (i < NBLK_SCAN) ? g_bsum[i] : 0;
    int lane = i & 31, w = i >> 5;
    int x = v;
    #pragma unroll
    for (int o = 1; o < 32; o <<= 1) {
        int y = __shfl_up_sync(~0u, x, o);
        if (lane >= o) x += y;
    }
    __shared__ int ws[8];
    if (lane == 31) ws[w] = x;
    __syncthreads();
    if (i < 8) {
        int s = ws[i];
        #pragma unroll
        for (int o = 1; o < 8; o <<= 1) {
            int y = __shfl_up_sync(0xff, s, o);
            if (i >= o) s += y;
        }
        ws[i] = s;
    }
    __syncthreads();
    int off = (w > 0) ? ws[w - 1] : 0;
    g_boff[i] = x + off - v;
}

__global__ void scan3_kernel() {
    int i = blockIdx.x * 256 + threadIdx.x;
    if (i < C_DIM) {
        int rs = g_local[i] + g_boff[i >> 8];
        g_rowstart[i] = rs;
        g_cursor[i]   = rs;
    }
    if (i == 0) g_rowstart[C_DIM] = E_TOT;
}

__global__ void build_kernel(const float* __restrict__ A_vals,
                             const float* __restrict__ vec,
                             const int* __restrict__ A_rows,
                             const int* __restrict__ A_cols) {
    int e = blockIdx.x * 256 + threadIdx.x;
    if (e >= E_TOT) return;
    int r = A_rows[e];
    int pos = atomicAdd(&g_cursor[r], 1);
    g_epack[pos] = make_uint2((uint32_t)A_cols[e],
                              __float_as_uint(A_vals[e] * __ldg(&vec[e / NNZ_G])));
}

// ---- SpMM (one n-half): warp per row, fp16 gather, fp32 accumulate -----
__global__ __launch_bounds__(256) void spmm_kernel(int nhalf) {
    int row = blockIdx.x * 8 + (threadIdx.x >> 5);
    if (row >= C_DIM) return;
    int lane = threadIdx.x & 31;
    int beg = g_rowstart[row], end = g_rowstart[row + 1];
    const uint2* E = g_epack;
    int nb = nhalf * 128;

    // residual Z init (fp32, exact)
    float4 acc = ((const float4*)(g_Zt + (size_t)row * N_B + nb))[lane];

    const __half* Zh = g_Zh + nb;
    int e = beg;
    for (; e + 4 <= end; e += 4) {
        uint2 p0 = E[e], p1 = E[e + 1], p2 = E[e + 2], p3 = E[e + 3];
        uint2 h0 = ((const uint2*)(Zh + (size_t)p0.x * N_B))[lane];
        uint2 h1 = ((const uint2*)(Zh + (size_t)p1.x * N_B))[lane];
        uint2 h2 = ((const uint2*)(Zh + (size_t)p2.x * N_B))[lane];
        uint2 h3 = ((const uint2*)(Zh + (size_t)p3.x * N_B))[lane];
        float w0 = __uint_as_float(p0.y), w1 = __uint_as_float(p1.y);
        float w2 = __uint_as_float(p2.y), w3 = __uint_as_float(p3.y);
        float2 a, b;
        a = __half22float2(*(__half2*)&h0.x); b = __half22float2(*(__half2*)&h0.y);
        acc.x = fmaf(w0, a.x, acc.x); acc.y = fmaf(w0, a.y, acc.y);
        acc.z = fmaf(w0, b.x, acc.z); acc.w = fmaf(w0, b.y, acc.w);
        a = __half22float2(*(__half2*)&h1.x); b = __half22float2(*(__half2*)&h1.y);
        acc.x = fmaf(w1, a.x, acc.x); acc.y = fmaf(w1, a.y, acc.y);
        acc.z = fmaf(w1, b.x, acc.z); acc.w = fmaf(w1, b.y, acc.w);
        a = __half22float2(*(__half2*)&h2.x); b = __half22float2(*(__half2*)&h2.y);
        acc.x = fmaf(w2, a.x, acc.x); acc.y = fmaf(w2, a.y, acc.y);
        acc.z = fmaf(w2, b.x, acc.z); acc.w = fmaf(w2, b.y, acc.w);
        a = __half22float2(*(__half2*)&h3.x); b = __half22float2(*(__half2*)&h3.y);
        acc.x = fmaf(w3, a.x, acc.x); acc.y = fmaf(w3, a.y, acc.y);
        acc.z = fmaf(w3, b.x, acc.z); acc.w = fmaf(w3, b.y, acc.w);
    }
    for (; e < end; e++) {
        uint2 p = E[e];
        float w = __uint_as_float(p.y);
        uint2 h = ((const uint2*)(Zh + (size_t)p.x * N_B))[lane];
        float2 a = __half22float2(*(__half2*)&h.x);
        float2 b = __half22float2(*(__half2*)&h.y);
        acc.x = fmaf(w, a.x, acc.x); acc.y = fmaf(w, a.y, acc.y);
        acc.z = fmaf(w, b.x, acc.z); acc.w = fmaf(w, b.y, acc.w);
    }
    ((float4*)(g_NT + (size_t)row * N_B + nb))[lane] = acc;
}

// -------- transpose NT -> out [N, C] (one n-half) -----------------------
__global__ void out_kernel(float* __restrict__ out, int nhalf) {
    __shared__ float tile[32][33];
    int c0 = blockIdx.x * 32, b0 = nhalf * 128 + blockIdx.y * 32;
    int tx = threadIdx.x & 31, ty = threadIdx.x >> 5;
    for (int j = ty; j < 32; j += 8) {
        int c = c0 + j;
        tile[j][tx] = (c < C_DIM) ? g_NT[(size_t)c * N_B + b0 + tx] : 0.f;
    }
    __syncthreads();
    for (int j = ty; j < 32; j += 8) {
        int c = c0 + tx;
        if (c < C_DIM)
            out[(size_t)(b0 + j) * C_DIM + c] = tile[tx][j];
    }
}

// ---------------- launch: forked-stream pipeline ------------------------
extern "C" void kernel_launch(void* const* d_in, const int* in_sizes, int n_in,
                              void* d_out, int out_size) {
    const float* output = (const float*)d_in[0];
    const float* wt2_w  = (const float*)d_in[1];
    const float* wt2_b  = (const float*)d_in[2];
    const float* A_vals = (const float*)d_in[3];
    const float* vec    = (const float*)d_in[4];
    const int*   A_rows = (const int*)d_in[5];
    const int*   A_cols = (const int*)d_in[6];
    float* out = (float*)d_out;

    static cudaStream_t sCsr = nullptr, sAux = nullptr;
    static cudaEvent_t evFork = nullptr, evCsr = nullptr, evGemmA = nullptr,
                       evAux = nullptr;
    if (!sCsr) {
        cudaStreamCreateWithFlags(&sCsr, cudaStreamNonBlocking);
        cudaStreamCreateWithFlags(&sAux, cudaStreamNonBlocking);
        cudaEventCreateWithFlags(&evFork, cudaEventDisableTiming);
        cudaEventCreateWithFlags(&evCsr, cudaEventDisableTiming);
        cudaEventCreateWithFlags(&evGemmA, cudaEventDisableTiming);
        cudaEventCreateWithFlags(&evAux, cudaEventDisableTiming);
        cudaFuncSetAttribute(mma_gemm,
                             cudaFuncAttributeMaxDynamicSharedMemorySize,
                             GEMM_SMEM);
    }

    int egrid = (E_TOT + 255) / 256;

    // fork
    cudaEventRecord(evFork, 0);
    cudaStreamWaitEvent(sCsr, evFork, 0);
    cudaStreamWaitEvent(sAux, evFork, 0);

    // CSR build on its own stream (independent of dense chain)
    zero_cnt_kernel<<<NBLK_SCAN, 256, 0, sCsr>>>();
    hist_kernel<<<egrid, 256, 0, sCsr>>>(A_rows);
    scan1_kernel<<<NBLK_SCAN, 256, 0, sCsr>>>();
    scan2_kernel<<<1, 256, 0, sCsr>>>();
    scan3_kernel<<<NBLK_SCAN, 256, 0, sCsr>>>();
    build_kernel<<<egrid, 256, 0, sCsr>>>(A_vals, vec, A_rows, A_cols);
    cudaEventRecord(evCsr, sCsr);

    // dense chain on main stream
    stats_kernel<<<D_K / 32, 256>>>(output);
    bconv_kernel<<<NCH, 256>>>(output);
    mma_gemm<<<NTILES, 256, GEMM_SMEM>>>(wt2_w, wt2_b, 0);      // n-half 0
    cudaEventRecord(evGemmA, 0);
    mma_gemm<<<NTILES, 256, GEMM_SMEM>>>(wt2_w, wt2_b, 128);    // n-half 1

    // aux stream: half-0 spmm + transpose, overlapped with gemm half-1
    cudaStreamWaitEvent(sAux, evGemmA, 0);
    cudaStreamWaitEvent(sAux, evCsr, 0);
    spmm_kernel<<<(C_DIM + 7) / 8, 256, 0, sAux>>>(0);
    out_kernel<<<dim3((C_DIM + 31) / 32, 4), 256, 0, sAux>>>(out, 0);
    cudaEventRecord(evAux, sAux);

    // main stream: half-1 spmm + transpose after gemm half-1
    cudaStreamWaitEvent(0, evCsr, 0);
    spmm_kernel<<<(C_DIM + 7) / 8, 256>>>(1);
    out_kernel<<<dim3((C_DIM + 31) / 32, 4), 256>>>(out, 1);

    // join
    cudaStreamWaitEvent(0, evAux, 0);
}

// round 7
// speedup vs baseline: 3.8954x; 1.1870x over previous
#include <cuda_runtime.h>
#include <cuda_fp16.h>
#include <cstdint>

#define N_B   256
#define D_K   1024
#define C_DIM 50000
#define G_N   4
#define NNZ_G 300000
#define E_TOT (G_N * NNZ_G)
#define NBLK_SCAN ((C_DIM + 255) / 256)   // 196

#define KC    64
#define NCH   (D_K / KC)                  // 16
#define TILE_C 128
#define NTILES ((C_DIM + TILE_C - 1) / TILE_C)  // 391
#define GEMM_SMEM 65536                   // (A 16K + B 16K) x 2 stages

// ---------------- scratch (static __device__, no allocs) ----------------
__device__ float  g_mean[D_K];
__device__ float  g_rstd[D_K];
__device__ float  g_Zt[(size_t)C_DIM * N_B];  // Z (fp32) for exact residual
__device__ __half g_Zh[(size_t)C_DIM * N_B];  // Z (fp16) gather image
// B image: per 64k-chunk, 256 m-rows x 128B fp16, SW128-swizzled
__device__ unsigned char g_B[NCH * N_B * 128];

// CSR build scratch
__device__ int   g_cnt[C_DIM];
__device__ int   g_local[C_DIM];
__device__ int   g_bsum[256];
__device__ int   g_boff[256];
__device__ int   g_rowstart[C_DIM + 1];
__device__ int   g_cursor[C_DIM];
__device__ uint2 g_epack[E_TOT];           // (col, weight-bits)

// ---------------- helpers ----------------------------------------------
__device__ __forceinline__ uint32_t smem_u32(const void* p) {
    uint32_t a;
    asm("{ .reg .u64 t; cvta.to.shared.u64 t, %1; cvt.u32.u64 %0, t; }"
        : "=r"(a) : "l"(p));
    return a;
}
#define SW128(o) ((o) ^ (((o) >> 3) & 0x70))

#define LDSM4(f, addr) \
    asm volatile("ldmatrix.sync.aligned.m8n8.x4.shared.b16 {%0,%1,%2,%3}, [%4];" \
        : "=r"((f)[0]), "=r"((f)[1]), "=r"((f)[2]), "=r"((f)[3]) : "r"(addr))
#define LDSM2(f, addr) \
    asm volatile("ldmatrix.sync.aligned.m8n8.x2.shared.b16 {%0,%1}, [%2];" \
        : "=r"((f)[0]), "=r"((f)[1]) : "r"(addr))
#define MMAF16(d, a, b) \
    asm volatile("mma.sync.aligned.m16n8k16.row.col.f32.f16.f16.f32 " \
        "{%0,%1,%2,%3}, {%4,%5,%6,%7}, {%8,%9}, {%0,%1,%2,%3};" \
        : "+f"((d)[0]), "+f"((d)[1]), "+f"((d)[2]), "+f"((d)[3]) \
        : "r"((a)[0]), "r"((a)[1]), "r"((a)[2]), "r"((a)[3]), \
          "r"((b)[0]), "r"((b)[1]))
#define CP_ASYNC16(dst, src) \
    asm volatile("cp.async.cg.shared.global [%0], [%1], 16;" :: "r"(dst), "l"(src))
#define CP_COMMIT() asm volatile("cp.async.commit_group;" ::: "memory")
#define CP_WAIT0()  asm volatile("cp.async.wait_group 0;"  ::: "memory")

__device__ __forceinline__ uint32_t h2pack(float a, float b) {
    __half2 t = __floats2half2_rn(a, b);
    return *(uint32_t*)&t;
}
__device__ __forceinline__ float swishf(float h) {
    return h * (1.f / (1.f + __expf(-h)));
}

// ---------------- kernel 1: batch stats (mean, rstd) --------------------
__global__ void stats_kernel(const float* __restrict__ x) {
    int tx = threadIdx.x & 31, ty = threadIdx.x >> 5;
    int c = blockIdx.x * 32 + tx;
    float s = 0.f, sq = 0.f;
    for (int r = ty; r < N_B; r += 8) {
        float v = x[r * D_K + c];
        s += v; sq += v * v;
    }
    __shared__ float ss[8][32], s2[8][32];
    ss[ty][tx] = s; s2[ty][tx] = sq;
    __syncthreads();
    if (ty == 0) {
        #pragma unroll
        for (int j = 1; j < 8; j++) { s += ss[j][tx]; sq += s2[j][tx]; }
        float mean = s * (1.f / N_B);
        float var  = sq * (1.f / N_B) - mean * mean;
        g_mean[c] = mean;
        g_rstd[c] = rsqrtf(var + 1e-5f);
    }
}

// ---------- kernel 2: normalize -> fp16 swizzled B image ----------------
__global__ void bconv_kernel(const float* __restrict__ x) {
    int id = blockIdx.x * 256 + threadIdx.x;   // 8192 threads
    int ch   = id >> 9;
    int m    = (id >> 1) & 255;
    int half = id & 1;
    int kb = ch * KC + half * 32;
    float v[32];
    #pragma unroll
    for (int q = 0; q < 8; q++) {
        float4 a  = *(const float4*)(x + m * D_K + kb + q * 4);
        float4 mu = *(const float4*)(g_mean + kb + q * 4);
        float4 rs = *(const float4*)(g_rstd + kb + q * 4);
        v[q * 4 + 0] = (a.x - mu.x) * rs.x;
        v[q * 4 + 1] = (a.y - mu.y) * rs.y;
        v[q * 4 + 2] = (a.z - mu.z) * rs.z;
        v[q * 4 + 3] = (a.w - mu.w) * rs.w;
    }
    unsigned char* base = g_B + (size_t)ch * (N_B * 128) + m * 128;
    int rot = m & 7;
    #pragma unroll
    for (int j = 0; j < 4; j++) {
        uint4 u = make_uint4(h2pack(v[8 * j + 0], v[8 * j + 1]),
                             h2pack(v[8 * j + 2], v[8 * j + 3]),
                             h2pack(v[8 * j + 4], v[8 * j + 5]),
                             h2pack(v[8 * j + 6], v[8 * j + 7]));
        *(uint4*)(base + (((half * 4 + j) ^ rot) << 4)) = u;
    }
}

// ---------------- kernel 3: fp16 mma.sync GEMM + bias + swish -----------
// Zt/Zh[c][m] = swish( sum_k W[c][k] * h0n[m][k] + bias[c] )
__global__ __launch_bounds__(256) void mma_gemm(const float* __restrict__ W,
                                                const float* __restrict__ bias) {
    extern __shared__ char smem[];
    uint32_t sb = smem_u32(smem);
    int tid = threadIdx.x, lane = tid & 31, warp = tid >> 5;
    int c0 = blockIdx.x * TILE_C;
    int m0 = blockIdx.y * 128;
    int warp_c = warp & 1, warp_m = warp >> 1;

    // staging identity: thread -> (A row r, 32-k half of the 64-k chunk)
    int r = tid >> 1, half = tid & 1;
    bool valid = (c0 + r) < C_DIM;
    const float* wsrc = W + (size_t)(c0 + r) * D_K + half * 32;
    int rot = r & 7;
    const unsigned char* gB_slice = g_B + (size_t)m0 * 128;  // CTA's 16K slice/chunk

    // ldmatrix lane address components
    uint32_t a_row = (uint32_t)(warp_c * 64 + (lane & 7) + ((lane & 8) ? 8 : 0));
    uint32_t a_sel = (lane & 16) ? 16u : 0u;
    uint32_t b_row = (uint32_t)(warp_m * 32 + (lane & 7));
    uint32_t b_sel = (lane & 8) ? 16u : 0u;

    float acc[4][4][4];
    #pragma unroll
    for (int i = 0; i < 4; i++)
        #pragma unroll
        for (int j = 0; j < 4; j++)
            #pragma unroll
            for (int q = 0; q < 4; q++) acc[i][j][q] = 0.f;

    // ---- prologue: stage chunk 0 into buffer 0 ----
    {
        uint32_t Bb = sb + 16384;
        #pragma unroll
        for (int i = 0; i < 4; i++) {
            int u = tid + 256 * i;
            CP_ASYNC16(Bb + u * 16, gB_slice + u * 16);
        }
        CP_COMMIT();
        char* smA = smem;
        #pragma unroll
        for (int j = 0; j < 4; j++) {
            float4 va = valid ? *(const float4*)(wsrc + j * 8)
                              : make_float4(0.f, 0.f, 0.f, 0.f);
            float4 vb = valid ? *(const float4*)(wsrc + j * 8 + 4)
                              : make_float4(0.f, 0.f, 0.f, 0.f);
            uint4 u = make_uint4(h2pack(va.x, va.y), h2pack(va.z, va.w),
                                 h2pack(vb.x, vb.y), h2pack(vb.z, vb.w));
            *(uint4*)(smA + r * 128 + (((half * 4 + j) ^ rot) << 4)) = u;
        }
        CP_WAIT0();
        __syncthreads();
    }

    for (int ch = 0; ch < NCH; ch++) {
        int nb = (ch + 1) & 1;
        bool has_next = (ch + 1) < NCH;
        float4 pre[8];
        if (has_next) {
            uint32_t Bb = sb + nb * 32768 + 16384;
            const unsigned char* src =
                gB_slice + (size_t)(ch + 1) * (N_B * 128);
            #pragma unroll
            for (int i = 0; i < 4; i++) {
                int u = tid + 256 * i;
                CP_ASYNC16(Bb + u * 16, src + u * 16);
            }
            CP_COMMIT();
            if (valid) {
                const float* s = wsrc + (ch + 1) * KC;
                #pragma unroll
                for (int j = 0; j < 8; j++) pre[j] = *(const float4*)(s + j * 4);
            } else {
                #pragma unroll
                for (int j = 0; j < 8; j++)
                    pre[j] = make_float4(0.f, 0.f, 0.f, 0.f);
            }
        }

        // ---- compute chunk ch from buffer ch&1 (K=64 -> 4 k-steps) ----
        uint32_t Ab = sb + (ch & 1) * 32768;
        uint32_t Bb = Ab + 16384;
        #pragma unroll
        for (int s = 0; s < 4; s++) {
            uint32_t af[4][4], bf[4][2];
            #pragma unroll
            for (int t = 0; t < 4; t++) {
                uint32_t o = (a_row + t * 16) * 128 + s * 32 + a_sel;
                LDSM4(af[t], Ab + SW128(o));
            }
            #pragma unroll
            for (int t = 0; t < 4; t++) {
                uint32_t o = (b_row + t * 8) * 128 + s * 32 + b_sel;
                LDSM2(bf[t], Bb + SW128(o));
            }
            #pragma unroll
            for (int ct = 0; ct < 4; ct++)
                #pragma unroll
                for (int mt = 0; mt < 4; mt++)
                    MMAF16(acc[ct][mt], af[ct], bf[mt]);
        }

        if (has_next) {
            char* smA = smem + nb * 32768;
            #pragma unroll
            for (int j = 0; j < 4; j++) {
                float4 va = pre[2 * j], vb = pre[2 * j + 1];
                uint4 u = make_uint4(h2pack(va.x, va.y), h2pack(va.z, va.w),
                                     h2pack(vb.x, vb.y), h2pack(vb.z, vb.w));
                *(uint4*)(smA + r * 128 + (((half * 4 + j) ^ rot) << 4)) = u;
            }
        }
        CP_WAIT0();
        __syncthreads();
    }

    // ---- epilogue: bias + swish -> Zt (fp32) + Zh (fp16) ----
    #pragma unroll
    for (int ct = 0; ct < 4; ct++) {
        int crow = c0 + warp_c * 64 + ct * 16 + (lane >> 2);
        float bv0 = (crow < C_DIM) ? __ldg(bias + crow) : 0.f;
        float bv1 = (crow + 8 < C_DIM) ? __ldg(bias + crow + 8) : 0.f;
        #pragma unroll
        for (int mt = 0; mt < 4; mt++) {
            int m = m0 + warp_m * 32 + mt * 8 + 2 * (lane & 3);
            float* d = acc[ct][mt];
            if (crow < C_DIM) {
                float z0 = swishf(d[0] + bv0), z1 = swishf(d[1] + bv0);
                *(float2*)(g_Zt + (size_t)crow * N_B + m) = make_float2(z0, z1);
                *(uint32_t*)(g_Zh + (size_t)crow * N_B + m) = h2pack(z0, z1);
            }
            if (crow + 8 < C_DIM) {
                float z2 = swishf(d[2] + bv1), z3 = swishf(d[3] + bv1);
                *(float2*)(g_Zt + (size_t)(crow + 8) * N_B + m) =
                    make_float2(z2, z3);
                *(uint32_t*)(g_Zh + (size_t)(crow + 8) * N_B + m) =
                    h2pack(z2, z3);
            }
        }
    }
}

// ---------------- CSR build: zero, hist, scan x3, bucket-scatter --------
__global__ void zero_cnt_kernel() {
    int i = blockIdx.x * 256 + threadIdx.x;
    if (i < C_DIM) g_cnt[i] = 0;
}

__global__ void hist_kernel(const int* __restrict__ A_rows) {
    int e = blockIdx.x * 256 + threadIdx.x;
    if (e < E_TOT) atomicAdd(&g_cnt[A_rows[e]], 1);
}

__global__ void scan1_kernel() {
    int i = blockIdx.x * 256 + threadIdx.x;
    int v = (i < C_DIM) ? g_cnt[i] : 0;
    int lane = threadIdx.x & 31, w = threadIdx.x >> 5;
    int x = v;
    #pragma unroll
    for (int o = 1; o < 32; o <<= 1) {
        int y = __shfl_up_sync(~0u, x, o);
        if (lane >= o) x += y;
    }
    __shared__ int ws[8];
    if (lane == 31) ws[w] = x;
    __syncthreads();
    if (threadIdx.x < 8) {
        int s = ws[threadIdx.x];
        #pragma unroll
        for (int o = 1; o < 8; o <<= 1) {
            int y = __shfl_up_sync(0xff, s, o);
            if ((int)threadIdx.x >= o) s += y;
        }
        ws[threadIdx.x] = s;
    }
    __syncthreads();
    int off = (w > 0) ? ws[w - 1] : 0;
    int incl = x + off;
    if (i < C_DIM) g_local[i] = incl - v;
    if (threadIdx.x == 255) g_bsum[blockIdx.x] = incl;
}

__global__ void scan2_kernel() {
    int i = threadIdx.x;
    int v = (i < NBLK_SCAN) ? g_bsum[i] : 0;
    int lane = i & 31, w = i >> 5;
    int x = v;
    #pragma unroll
    for (int o = 1; o < 32; o <<= 1) {
        int y = __shfl_up_sync(~0u, x, o);
        if (lane >= o) x += y;
    }
    __shared__ int ws[8];
    if (lane == 31) ws[w] = x;
    __syncthreads();
    if (i < 8) {
        int s = ws[i];
        #pragma unroll
        for (int o = 1; o < 8; o <<= 1) {
            int y = __shfl_up_sync(0xff, s, o);
            if (i >= o) s += y;
        }
        ws[i] = s;
    }
    __syncthreads();
    int off = (w > 0) ? ws[w - 1] : 0;
    g_boff[i] = x + off - v;
}

__global__ void scan3_kernel() {
    int i = blockIdx.x * 256 + threadIdx.x;
    if (i < C_DIM) {
        int rs = g_local[i] + g_boff[i >> 8];
        g_rowstart[i] = rs;
        g_cursor[i]   = rs;
    }
    if (i == 0) g_rowstart[C_DIM] = E_TOT;
}

__global__ void build_kernel(const float* __restrict__ A_vals,
                             const float* __restrict__ vec,
                             const int* __restrict__ A_rows,
                             const int* __restrict__ A_cols) {
    int e = blockIdx.x * 256 + threadIdx.x;
    if (e >= E_TOT) return;
    int r = A_rows[e];
    int pos = atomicAdd(&g_cursor[r], 1);
    g_epack[pos] = make_uint2((uint32_t)A_cols[e],
                              __float_as_uint(A_vals[e] * __ldg(&vec[e / NNZ_G])));
}

// ---- fused SpMM + transpose-out: warp per row, fp16 gather -------------
__global__ __launch_bounds__(256) void spmm_out_kernel(float* __restrict__ out) {
    __shared__ float sm[8][256];
    int wid = threadIdx.x >> 5, lane = threadIdx.x & 31;
    int row = blockIdx.x * 8 + wid;
    int beg = g_rowstart[row], end = g_rowstart[row + 1];
    const uint2* E = g_epack;

    // residual Z init (fp32, exact); lane covers n = lane*8 .. lane*8+7
    float acc[8];
    {
        const float4* zr = (const float4*)(g_Zt + (size_t)row * N_B);
        float4 q0 = zr[lane * 2], q1 = zr[lane * 2 + 1];
        acc[0] = q0.x; acc[1] = q0.y; acc[2] = q0.z; acc[3] = q0.w;
        acc[4] = q1.x; acc[5] = q1.y; acc[6] = q1.z; acc[7] = q1.w;
    }

    int e = beg;
    for (; e + 4 <= end; e += 4) {
        uint2 p0 = E[e], p1 = E[e + 1], p2 = E[e + 2], p3 = E[e + 3];
        uint4 h0 = ((const uint4*)(g_Zh + (size_t)p0.x * N_B))[lane];
        uint4 h1 = ((const uint4*)(g_Zh + (size_t)p1.x * N_B))[lane];
        uint4 h2 = ((const uint4*)(g_Zh + (size_t)p2.x * N_B))[lane];
        uint4 h3 = ((const uint4*)(g_Zh + (size_t)p3.x * N_B))[lane];
        float w0 = __uint_as_float(p0.y), w1 = __uint_as_float(p1.y);
        float w2 = __uint_as_float(p2.y), w3 = __uint_as_float(p3.y);
        #pragma unroll
        for (int q = 0; q < 4; q++) {
            float2 a;
            a = __half22float2(*(__half2*)((uint32_t*)&h0 + q));
            acc[2 * q] = fmaf(w0, a.x, acc[2 * q]);
            acc[2 * q + 1] = fmaf(w0, a.y, acc[2 * q + 1]);
            a = __half22float2(*(__half2*)((uint32_t*)&h1 + q));
            acc[2 * q] = fmaf(w1, a.x, acc[2 * q]);
            acc[2 * q + 1] = fmaf(w1, a.y, acc[2 * q + 1]);
            a = __half22float2(*(__half2*)((uint32_t*)&h2 + q));
            acc[2 * q] = fmaf(w2, a.x, acc[2 * q]);
            acc[2 * q + 1] = fmaf(w2, a.y, acc[2 * q + 1]);
            a = __half22float2(*(__half2*)((uint32_t*)&h3 + q));
            acc[2 * q] = fmaf(w3, a.x, acc[2 * q]);
            acc[2 * q + 1] = fmaf(w3, a.y, acc[2 * q + 1]);
        }
    }
    for (; e < end; e++) {
        uint2 p = E[e];
        float w = __uint_as_float(p.y);
        uint4 h = ((const uint4*)(g_Zh + (size_t)p.x * N_B))[lane];
        #pragma unroll
        for (int q = 0; q < 4; q++) {
            float2 a = __half22float2(*(__half2*)((uint32_t*)&h + q));
            acc[2 * q] = fmaf(w, a.x, acc[2 * q]);
            acc[2 * q + 1] = fmaf(w, a.y, acc[2 * q + 1]);
        }
    }

    // stage and transpose: sm[row_local][n]
    #pragma unroll
    for (int j = 0; j < 8; j++) sm[wid][lane * 8 + j] = acc[j];
    __syncthreads();

    int n = threadIdx.x;
    int cb = blockIdx.x * 8;
    float v[8];
    #pragma unroll
    for (int j = 0; j < 8; j++) v[j] = sm[j][n];
    float* dst = out + (size_t)n * C_DIM + cb;
    *(float4*)(dst)     = make_float4(v[0], v[1], v[2], v[3]);
    *(float4*)(dst + 4) = make_float4(v[4], v[5], v[6], v[7]);
}

// ---------------- launch: forked CSR stream + dense chain ---------------
extern "C" void kernel_launch(void* const* d_in, const int* in_sizes, int n_in,
                              void* d_out, int out_size) {
    const float* output = (const float*)d_in[0];
    const float* wt2_w  = (const float*)d_in[1];
    const float* wt2_b  = (const float*)d_in[2];
    const float* A_vals = (const float*)d_in[3];
    const float* vec    = (const float*)d_in[4];
    const int*   A_rows = (const int*)d_in[5];
    const int*   A_cols = (const int*)d_in[6];
    float* out = (float*)d_out;

    static cudaStream_t sCsr = nullptr;
    static cudaEvent_t evFork = nullptr, evCsr = nullptr;
    if (!sCsr) {
        cudaStreamCreateWithFlags(&sCsr, cudaStreamNonBlocking);
        cudaEventCreateWithFlags(&evFork, cudaEventDisableTiming);
        cudaEventCreateWithFlags(&evCsr, cudaEventDisableTiming);
        cudaFuncSetAttribute(mma_gemm,
                             cudaFuncAttributeMaxDynamicSharedMemorySize,
                             GEMM_SMEM);
    }

    int egrid = (E_TOT + 255) / 256;

    // fork: CSR build runs concurrently with the dense chain
    cudaEventRecord(evFork, 0);
    cudaStreamWaitEvent(sCsr, evFork, 0);
    zero_cnt_kernel<<<NBLK_SCAN, 256, 0, sCsr>>>();
    hist_kernel<<<egrid, 256, 0, sCsr>>>(A_rows);
    scan1_kernel<<<NBLK_SCAN, 256, 0, sCsr>>>();
    scan2_kernel<<<1, 256, 0, sCsr>>>();
    scan3_kernel<<<NBLK_SCAN, 256, 0, sCsr>>>();
    build_kernel<<<egrid, 256, 0, sCsr>>>(A_vals, vec, A_rows, A_cols);
    cudaEventRecord(evCsr, sCsr);

    // dense chain
    stats_kernel<<<D_K / 32, 256>>>(output);
    bconv_kernel<<<32, 256>>>(output);
    mma_gemm<<<dim3(NTILES, 2), 256, GEMM_SMEM>>>(wt2_w, wt2_b);

    // join, then fused sparse aggregate + residual + transpose-out
    cudaStreamWaitEvent(0, evCsr, 0);
    spmm_out_kernel<<<C_DIM / 8, 256>>>(out);
}

// round 8
// speedup vs baseline: 4.0307x; 1.0347x over previous
#include <cuda_runtime.h>
#include <cuda_fp16.h>
#include <cstdint>

#define N_B   256
#define D_K   1024
#define C_DIM 50000
#define G_N   4
#define NNZ_G 300000
#define E_TOT (G_N * NNZ_G)
#define NBLK_SCAN ((C_DIM + 255) / 256)   // 196

#define KC    64
#define NCH   (D_K / KC)                  // 16
#define TILE_C 128
#define NTILES ((C_DIM + TILE_C - 1) / TILE_C)  // 391
#define GEMM_SMEM 65536                   // (A 16K + B 16K) x 2 stages

// ---------------- scratch (static __device__, no allocs) ----------------
__device__ float  g_mean[D_K];
__device__ float  g_rstd[D_K];
__device__ float  g_Zt[(size_t)C_DIM * N_B];  // Z (fp32) for exact residual
__device__ __half g_Zh[(size_t)C_DIM * N_B];  // Z (fp16) gather image
// B image: per 64k-chunk, 256 m-rows x 128B fp16, SW128-swizzled
__device__ unsigned char g_B[NCH * N_B * 128];

// CSR build scratch
__device__ int   g_cnt[C_DIM];
__device__ int   g_local[C_DIM];
__device__ int   g_bsum[256];
__device__ int   g_boff[256];
__device__ int   g_rowstart[C_DIM + 1];
__device__ int   g_cursor[C_DIM];
__device__ uint2 g_epack[E_TOT];           // (col, weight-bits)

// ---------------- helpers ----------------------------------------------
__device__ __forceinline__ uint32_t smem_u32(const void* p) {
    uint32_t a;
    asm("{ .reg .u64 t; cvta.to.shared.u64 t, %1; cvt.u32.u64 %0, t; }"
        : "=r"(a) : "l"(p));
    return a;
}
#define SW128(o) ((o) ^ (((o) >> 3) & 0x70))

#define LDSM4(f, addr) \
    asm volatile("ldmatrix.sync.aligned.m8n8.x4.shared.b16 {%0,%1,%2,%3}, [%4];" \
        : "=r"((f)[0]), "=r"((f)[1]), "=r"((f)[2]), "=r"((f)[3]) : "r"(addr))
#define LDSM2(f, addr) \
    asm volatile("ldmatrix.sync.aligned.m8n8.x2.shared.b16 {%0,%1}, [%2];" \
        : "=r"((f)[0]), "=r"((f)[1]) : "r"(addr))
#define MMAF16(d, a, b) \
    asm volatile("mma.sync.aligned.m16n8k16.row.col.f32.f16.f16.f32 " \
        "{%0,%1,%2,%3}, {%4,%5,%6,%7}, {%8,%9}, {%0,%1,%2,%3};" \
        : "+f"((d)[0]), "+f"((d)[1]), "+f"((d)[2]), "+f"((d)[3]) \
        : "r"((a)[0]), "r"((a)[1]), "r"((a)[2]), "r"((a)[3]), \
          "r"((b)[0]), "r"((b)[1]))
#define CP_ASYNC16(dst, src) \
    asm volatile("cp.async.cg.shared.global [%0], [%1], 16;" :: "r"(dst), "l"(src))
#define CP_COMMIT() asm volatile("cp.async.commit_group;" ::: "memory")
#define CP_WAIT0()  asm volatile("cp.async.wait_group 0;"  ::: "memory")

__device__ __forceinline__ uint32_t h2pack(float a, float b) {
    __half2 t = __floats2half2_rn(a, b);
    return *(uint32_t*)&t;
}
__device__ __forceinline__ float swishf(float h) {
    return h * (1.f / (1.f + __expf(-h)));
}

// ---------------- kernel 1: batch stats (mean, rstd) --------------------
__global__ void stats_kernel(const float* __restrict__ x) {
    int tx = threadIdx.x & 31, ty = threadIdx.x >> 5;
    int c = blockIdx.x * 32 + tx;
    float s = 0.f, sq = 0.f;
    for (int r = ty; r < N_B; r += 8) {
        float v = x[r * D_K + c];
        s += v; sq += v * v;
    }
    __shared__ float ss[8][32], s2[8][32];
    ss[ty][tx] = s; s2[ty][tx] = sq;
    __syncthreads();
    if (ty == 0) {
        #pragma unroll
        for (int j = 1; j < 8; j++) { s += ss[j][tx]; sq += s2[j][tx]; }
        float mean = s * (1.f / N_B);
        float var  = sq * (1.f / N_B) - mean * mean;
        g_mean[c] = mean;
        g_rstd[c] = rsqrtf(var + 1e-5f);
    }
}

// ---------- kernel 2: normalize -> fp16 swizzled B image ----------------
__global__ void bconv_kernel(const float* __restrict__ x) {
    int id = blockIdx.x * 256 + threadIdx.x;   // 8192 threads
    int ch   = id >> 9;
    int m    = (id >> 1) & 255;
    int half = id & 1;
    int kb = ch * KC + half * 32;
    float v[32];
    #pragma unroll
    for (int q = 0; q < 8; q++) {
        float4 a  = *(const float4*)(x + m * D_K + kb + q * 4);
        float4 mu = *(const float4*)(g_mean + kb + q * 4);
        float4 rs = *(const float4*)(g_rstd + kb + q * 4);
        v[q * 4 + 0] = (a.x - mu.x) * rs.x;
        v[q * 4 + 1] = (a.y - mu.y) * rs.y;
        v[q * 4 + 2] = (a.z - mu.z) * rs.z;
        v[q * 4 + 3] = (a.w - mu.w) * rs.w;
    }
    unsigned char* base = g_B + (size_t)ch * (N_B * 128) + m * 128;
    int rot = m & 7;
    #pragma unroll
    for (int j = 0; j < 4; j++) {
        uint4 u = make_uint4(h2pack(v[8 * j + 0], v[8 * j + 1]),
                             h2pack(v[8 * j + 2], v[8 * j + 3]),
                             h2pack(v[8 * j + 4], v[8 * j + 5]),
                             h2pack(v[8 * j + 6], v[8 * j + 7]));
        *(uint4*)(base + (((half * 4 + j) ^ rot) << 4)) = u;
    }
}

// ------- kernel 3: fp16 mma.sync GEMM + bias + swish (one m-half) -------
__global__ __launch_bounds__(256) void mma_gemm(const float* __restrict__ W,
                                                const float* __restrict__ bias,
                                                int m0) {
    extern __shared__ char smem[];
    uint32_t sb = smem_u32(smem);
    int tid = threadIdx.x, lane = tid & 31, warp = tid >> 5;
    int c0 = blockIdx.x * TILE_C;
    int warp_c = warp & 1, warp_m = warp >> 1;

    // staging identity: thread -> (A row r, 32-k half of the 64-k chunk)
    int r = tid >> 1, half = tid & 1;
    bool valid = (c0 + r) < C_DIM;
    const float* wsrc = W + (size_t)(c0 + r) * D_K + half * 32;
    int rot = r & 7;
    const unsigned char* gB_slice = g_B + (size_t)m0 * 128;  // 16K slice/chunk

    // ldmatrix lane address components
    uint32_t a_row = (uint32_t)(warp_c * 64 + (lane & 7) + ((lane & 8) ? 8 : 0));
    uint32_t a_sel = (lane & 16) ? 16u : 0u;
    uint32_t b_row = (uint32_t)(warp_m * 32 + (lane & 7));
    uint32_t b_sel = (lane & 8) ? 16u : 0u;

    float acc[4][4][4];
    #pragma unroll
    for (int i = 0; i < 4; i++)
        #pragma unroll
        for (int j = 0; j < 4; j++)
            #pragma unroll
            for (int q = 0; q < 4; q++) acc[i][j][q] = 0.f;

    // ---- prologue: stage chunk 0 into buffer 0 ----
    {
        uint32_t Bb = sb + 16384;
        #pragma unroll
        for (int i = 0; i < 4; i++) {
            int u = tid + 256 * i;
            CP_ASYNC16(Bb + u * 16, gB_slice + u * 16);
        }
        CP_COMMIT();
        char* smA = smem;
        #pragma unroll
        for (int j = 0; j < 4; j++) {
            float4 va = valid ? *(const float4*)(wsrc + j * 8)
                              : make_float4(0.f, 0.f, 0.f, 0.f);
            float4 vb = valid ? *(const float4*)(wsrc + j * 8 + 4)
                              : make_float4(0.f, 0.f, 0.f, 0.f);
            uint4 u = make_uint4(h2pack(va.x, va.y), h2pack(va.z, va.w),
                                 h2pack(vb.x, vb.y), h2pack(vb.z, vb.w));
            *(uint4*)(smA + r * 128 + (((half * 4 + j) ^ rot) << 4)) = u;
        }
        CP_WAIT0();
        __syncthreads();
    }

    for (int ch = 0; ch < NCH; ch++) {
        int nb = (ch + 1) & 1;
        bool has_next = (ch + 1) < NCH;
        float4 pre[8];
        if (has_next) {
            uint32_t Bb = sb + nb * 32768 + 16384;
            const unsigned char* src =
                gB_slice + (size_t)(ch + 1) * (N_B * 128);
            #pragma unroll
            for (int i = 0; i < 4; i++) {
                int u = tid + 256 * i;
                CP_ASYNC16(Bb + u * 16, src + u * 16);
            }
            CP_COMMIT();
            if (valid) {
                const float* s = wsrc + (ch + 1) * KC;
                #pragma unroll
                for (int j = 0; j < 8; j++) pre[j] = *(const float4*)(s + j * 4);
            } else {
                #pragma unroll
                for (int j = 0; j < 8; j++)
                    pre[j] = make_float4(0.f, 0.f, 0.f, 0.f);
            }
        }

        // ---- compute chunk ch from buffer ch&1 (K=64 -> 4 k-steps) ----
        uint32_t Ab = sb + (ch & 1) * 32768;
        uint32_t Bb = Ab + 16384;
        #pragma unroll
        for (int s = 0; s < 4; s++) {
            uint32_t af[4][4], bf[4][2];
            #pragma unroll
            for (int t = 0; t < 4; t++) {
                uint32_t o = (a_row + t * 16) * 128 + s * 32 + a_sel;
                LDSM4(af[t], Ab + SW128(o));
            }
            #pragma unroll
            for (int t = 0; t < 4; t++) {
                uint32_t o = (b_row + t * 8) * 128 + s * 32 + b_sel;
                LDSM2(bf[t], Bb + SW128(o));
            }
            #pragma unroll
            for (int ct = 0; ct < 4; ct++)
                #pragma unroll
                for (int mt = 0; mt < 4; mt++)
                    MMAF16(acc[ct][mt], af[ct], bf[mt]);
        }

        if (has_next) {
            char* smA = smem + nb * 32768;
            #pragma unroll
            for (int j = 0; j < 4; j++) {
                float4 va = pre[2 * j], vb = pre[2 * j + 1];
                uint4 u = make_uint4(h2pack(va.x, va.y), h2pack(va.z, va.w),
                                     h2pack(vb.x, vb.y), h2pack(vb.z, vb.w));
                *(uint4*)(smA + r * 128 + (((half * 4 + j) ^ rot) << 4)) = u;
            }
        }
        CP_WAIT0();
        __syncthreads();
    }

    // ---- epilogue: bias + swish -> Zt (fp32) + Zh (fp16) ----
    #pragma unroll
    for (int ct = 0; ct < 4; ct++) {
        int crow = c0 + warp_c * 64 + ct * 16 + (lane >> 2);
        float bv0 = (crow < C_DIM) ? __ldg(bias + crow) : 0.f;
        float bv1 = (crow + 8 < C_DIM) ? __ldg(bias + crow + 8) : 0.f;
        #pragma unroll
        for (int mt = 0; mt < 4; mt++) {
            int m = m0 + warp_m * 32 + mt * 8 + 2 * (lane & 3);
            float* d = acc[ct][mt];
            if (crow < C_DIM) {
                float z0 = swishf(d[0] + bv0), z1 = swishf(d[1] + bv0);
                *(float2*)(g_Zt + (size_t)crow * N_B + m) = make_float2(z0, z1);
                *(uint32_t*)(g_Zh + (size_t)crow * N_B + m) = h2pack(z0, z1);
            }
            if (crow + 8 < C_DIM) {
                float z2 = swishf(d[2] + bv1), z3 = swishf(d[3] + bv1);
                *(float2*)(g_Zt + (size_t)(crow + 8) * N_B + m) =
                    make_float2(z2, z3);
                *(uint32_t*)(g_Zh + (size_t)(crow + 8) * N_B + m) =
                    h2pack(z2, z3);
            }
        }
    }
}

// ---------------- CSR build: zero, hist, scan x3, bucket-scatter --------
__global__ void zero_cnt_kernel() {
    int i = blockIdx.x * 256 + threadIdx.x;
    if (i < C_DIM) g_cnt[i] = 0;
}

__global__ void hist_kernel(const int* __restrict__ A_rows) {
    int e = blockIdx.x * 256 + threadIdx.x;
    if (e < E_TOT) atomicAdd(&g_cnt[A_rows[e]], 1);
}

__global__ void scan1_kernel() {
    int i = blockIdx.x * 256 + threadIdx.x;
    int v = (i < C_DIM) ? g_cnt[i] : 0;
    int lane = threadIdx.x & 31, w = threadIdx.x >> 5;
    int x = v;
    #pragma unroll
    for (int o = 1; o < 32; o <<= 1) {
        int y = __shfl_up_sync(~0u, x, o);
        if (lane >= o) x += y;
    }
    __shared__ int ws[8];
    if (lane == 31) ws[w] = x;
    __syncthreads();
    if (threadIdx.x < 8) {
        int s = ws[threadIdx.x];
        #pragma unroll
        for (int o = 1; o < 8; o <<= 1) {
            int y = __shfl_up_sync(0xff, s, o);
            if ((int)threadIdx.x >= o) s += y;
        }
        ws[threadIdx.x] = s;
    }
    __syncthreads();
    int off = (w > 0) ? ws[w - 1] : 0;
    int incl = x + off;
    if (i < C_DIM) g_local[i] = incl - v;
    if (threadIdx.x == 255) g_bsum[blockIdx.x] = incl;
}

__global__ void scan2_kernel() {
    int i = threadIdx.x;
    int v = (i < NBLK_SCAN) ? g_bsum[i] : 0;
    int lane = i & 31, w = i >> 5;
    int x = v;
    #pragma unroll
    for (int o = 1; o < 32; o <<= 1) {
        int y = __shfl_up_sync(~0u, x, o);
        if (lane >= o) x += y;
    }
    __shared__ int ws[8];
    if (lane == 31) ws[w] = x;
    __syncthreads();
    if (i < 8) {
        int s = ws[i];
        #pragma unroll
        for (int o = 1; o < 8; o <<= 1) {
            int y = __shfl_up_sync(0xff, s, o);
            if (i >= o) s += y;
        }
        ws[i] = s;
    }
    __syncthreads();
    int off = (w > 0) ? ws[w - 1] : 0;
    g_boff[i] = x + off - v;
}

__global__ void scan3_kernel() {
    int i = blockIdx.x * 256 + threadIdx.x;
    if (i < C_DIM) {
        int rs = g_local[i] + g_boff[i >> 8];
        g_rowstart[i] = rs;
        g_cursor[i]   = rs;
    }
    if (i == 0) g_rowstart[C_DIM] = E_TOT;
}

__global__ void build_kernel(const float* __restrict__ A_vals,
                             const float* __restrict__ vec,
                             const int* __restrict__ A_rows,
                             const int* __restrict__ A_cols) {
    int e = blockIdx.x * 256 + threadIdx.x;
    if (e >= E_TOT) return;
    int r = A_rows[e];
    int pos = atomicAdd(&g_cursor[r], 1);
    g_epack[pos] = make_uint2((uint32_t)A_cols[e],
                              __float_as_uint(A_vals[e] * __ldg(&vec[e / NNZ_G])));
}

// -- fused SpMM + transpose-out (one n-half): warp per row, fp16 gather --
__global__ __launch_bounds__(256) void spmm_out_kernel(float* __restrict__ out,
                                                       int nhalf) {
    __shared__ float sm[8][132];
    int wid = threadIdx.x >> 5, lane = threadIdx.x & 31;
    int row = blockIdx.x * 8 + wid;
    int beg = g_rowstart[row], end = g_rowstart[row + 1];
    const uint2* E = g_epack;
    const __half* Zb = g_Zh + nhalf * 128;

    // residual Z init (fp32, exact); lane covers n-local = lane*4 .. +3
    float4 acc = *(const float4*)(g_Zt + (size_t)row * N_B + nhalf * 128 +
                                  lane * 4);

    int e = beg;
    for (; e + 4 <= end; e += 4) {
        uint2 p0 = E[e], p1 = E[e + 1], p2 = E[e + 2], p3 = E[e + 3];
        uint2 h0 = *(const uint2*)(Zb + (size_t)p0.x * N_B + lane * 4);
        uint2 h1 = *(const uint2*)(Zb + (size_t)p1.x * N_B + lane * 4);
        uint2 h2 = *(const uint2*)(Zb + (size_t)p2.x * N_B + lane * 4);
        uint2 h3 = *(const uint2*)(Zb + (size_t)p3.x * N_B + lane * 4);
        float w0 = __uint_as_float(p0.y), w1 = __uint_as_float(p1.y);
        float w2 = __uint_as_float(p2.y), w3 = __uint_as_float(p3.y);
        float2 a, b;
        a = __half22float2(*(__half2*)&h0.x); b = __half22float2(*(__half2*)&h0.y);
        acc.x = fmaf(w0, a.x, acc.x); acc.y = fmaf(w0, a.y, acc.y);
        acc.z = fmaf(w0, b.x, acc.z); acc.w = fmaf(w0, b.y, acc.w);
        a = __half22float2(*(__half2*)&h1.x); b = __half22float2(*(__half2*)&h1.y);
        acc.x = fmaf(w1, a.x, acc.x); acc.y = fmaf(w1, a.y, acc.y);
        acc.z = fmaf(w1, b.x, acc.z); acc.w = fmaf(w1, b.y, acc.w);
        a = __half22float2(*(__half2*)&h2.x); b = __half22float2(*(__half2*)&h2.y);
        acc.x = fmaf(w2, a.x, acc.x); acc.y = fmaf(w2, a.y, acc.y);
        acc.z = fmaf(w2, b.x, acc.z); acc.w = fmaf(w2, b.y, acc.w);
        a = __half22float2(*(__half2*)&h3.x); b = __half22float2(*(__half2*)&h3.y);
        acc.x = fmaf(w3, a.x, acc.x); acc.y = fmaf(w3, a.y, acc.y);
        acc.z = fmaf(w3, b.x, acc.z); acc.w = fmaf(w3, b.y, acc.w);
    }
    for (; e < end; e++) {
        uint2 p = E[e];
        float w = __uint_as_float(p.y);
        uint2 h = *(const uint2*)(Zb + (size_t)p.x * N_B + lane * 4);
        float2 a = __half22float2(*(__half2*)&h.x);
        float2 b = __half22float2(*(__half2*)&h.y);
        acc.x = fmaf(w, a.x, acc.x); acc.y = fmaf(w, a.y, acc.y);
        acc.z = fmaf(w, b.x, acc.z); acc.w = fmaf(w, b.y, acc.w);
    }

    // stage sm[c_local][n_local]
    sm[wid][lane * 4 + 0] = acc.x;
    sm[wid][lane * 4 + 1] = acc.y;
    sm[wid][lane * 4 + 2] = acc.z;
    sm[wid][lane * 4 + 3] = acc.w;
    __syncthreads();

    // transposed write: thread t -> n_local = t>>1, c quad = (t&1)*4
    int nl = threadIdx.x >> 1;
    int cq = (threadIdx.x & 1) * 4;
    float4 v = make_float4(sm[cq + 0][nl], sm[cq + 1][nl],
                           sm[cq + 2][nl], sm[cq + 3][nl]);
    *(float4*)(out + (size_t)(nhalf * 128 + nl) * C_DIM + blockIdx.x * 8 + cq) = v;
}

// ---------------- launch: forked pipeline (gemm0 at kernel index 3) -----
extern "C" void kernel_launch(void* const* d_in, const int* in_sizes, int n_in,
                              void* d_out, int out_size) {
    const float* output = (const float*)d_in[0];
    const float* wt2_w  = (const float*)d_in[1];
    const float* wt2_b  = (const float*)d_in[2];
    const float* A_vals = (const float*)d_in[3];
    const float* vec    = (const float*)d_in[4];
    const int*   A_rows = (const int*)d_in[5];
    const int*   A_cols = (const int*)d_in[6];
    float* out = (float*)d_out;

    static cudaStream_t sCsr = nullptr, sAux = nullptr;
    static cudaEvent_t evFork = nullptr, evCsr = nullptr, evG0 = nullptr,
                       evAux = nullptr;
    if (!sCsr) {
        cudaStreamCreateWithFlags(&sCsr, cudaStreamNonBlocking);
        cudaStreamCreateWithFlags(&sAux, cudaStreamNonBlocking);
        cudaEventCreateWithFlags(&evFork, cudaEventDisableTiming);
        cudaEventCreateWithFlags(&evCsr, cudaEventDisableTiming);
        cudaEventCreateWithFlags(&evG0, cudaEventDisableTiming);
        cudaEventCreateWithFlags(&evAux, cudaEventDisableTiming);
        cudaFuncSetAttribute(mma_gemm,
                             cudaFuncAttributeMaxDynamicSharedMemorySize,
                             GEMM_SMEM);
    }

    int egrid = (E_TOT + 255) / 256;

    cudaEventRecord(evFork, 0);
    cudaStreamWaitEvent(sCsr, evFork, 0);

    // submission order matters for ncu (-s lands on kernel index 3 = gemm0)
    stats_kernel<<<D_K / 32, 256>>>(output);                       // 0
    bconv_kernel<<<32, 256>>>(output);                             // 1
    zero_cnt_kernel<<<NBLK_SCAN, 256, 0, sCsr>>>();                // 2
    mma_gemm<<<NTILES, 256, GEMM_SMEM>>>(wt2_w, wt2_b, 0);         // 3 <- ncu
    cudaEventRecord(evG0, 0);
    hist_kernel<<<egrid, 256, 0, sCsr>>>(A_rows);                  // 4
    scan1_kernel<<<NBLK_SCAN, 256, 0, sCsr>>>();                   // 5
    scan2_kernel<<<1, 256, 0, sCsr>>>();                           // 6
    scan3_kernel<<<NBLK_SCAN, 256, 0, sCsr>>>();                   // 7
    build_kernel<<<egrid, 256, 0, sCsr>>>(A_vals, vec, A_rows, A_cols); // 8
    cudaEventRecord(evCsr, sCsr);

    mma_gemm<<<NTILES, 256, GEMM_SMEM>>>(wt2_w, wt2_b, 128);       // 9

    // aux: half-0 sparse work overlapped with gemm half-1
    cudaStreamWaitEvent(sAux, evG0, 0);
    cudaStreamWaitEvent(sAux, evCsr, 0);
    spmm_out_kernel<<<C_DIM / 8, 256, 0, sAux>>>(out, 0);          // 10
    cudaEventRecord(evAux, sAux);

    // main: half-1 sparse work after gemm half-1
    cudaStreamWaitEvent(0, evCsr, 0);
    spmm_out_kernel<<<C_DIM / 8, 256>>>(out, 1);                   // 11

    cudaStreamWaitEvent(0, evAux, 0);
}

// round 9
// speedup vs baseline: 5.2695x; 1.3074x over previous
#include <cuda_runtime.h>
#include <cuda_fp16.h>
#include <cstdint>

#define N_B   256
#define D_K   1024
#define C_DIM 50000
#define G_N   4
#define NNZ_G 300000
#define E_TOT (G_N * NNZ_G)
#define NBLK_SCAN ((C_DIM + 255) / 256)   // 196

#define KC    64
#define NCH   (D_K / KC)                  // 16
#define TILE_C 128
#define NTILES ((C_DIM + TILE_C - 1) / TILE_C)  // 391
#define GEMM_SMEM 98304                   // 3 stages x (A 16K + B 16K)

// ---------------- scratch (static __device__, no allocs) ----------------
__device__ float  g_mean[D_K];
__device__ float  g_rstd[D_K];
__device__ float  g_Zt[(size_t)C_DIM * N_B];  // Z (fp32) for exact residual
__device__ __half g_Zh[(size_t)C_DIM * N_B];  // Z (fp16) gather image
// B image: per 64k-chunk, 256 m-rows x 128B fp16, SW128-swizzled
__device__ unsigned char g_B[NCH * N_B * 128];
// W image: per (c-tile, chunk), 128 rows x 128B fp16, SW128-swizzled (100 MB)
__device__ unsigned char g_Wh[(size_t)NTILES * NCH * 16384];

// CSR build scratch
__device__ int   g_cnt[C_DIM];
__device__ int   g_local[C_DIM];
__device__ int   g_bsum[256];
__device__ int   g_boff[256];
__device__ int   g_rowstart[C_DIM + 1];
__device__ int   g_cursor[C_DIM];
__device__ uint2 g_epack[E_TOT];           // (col, weight-bits)

// ---------------- helpers ----------------------------------------------
__device__ __forceinline__ uint32_t smem_u32(const void* p) {
    uint32_t a;
    asm("{ .reg .u64 t; cvta.to.shared.u64 t, %1; cvt.u32.u64 %0, t; }"
        : "=r"(a) : "l"(p));
    return a;
}
#define SW128(o) ((o) ^ (((o) >> 3) & 0x70))

#define LDSM4(f, addr) \
    asm volatile("ldmatrix.sync.aligned.m8n8.x4.shared.b16 {%0,%1,%2,%3}, [%4];" \
        : "=r"((f)[0]), "=r"((f)[1]), "=r"((f)[2]), "=r"((f)[3]) : "r"(addr))
#define LDSM2(f, addr) \
    asm volatile("ldmatrix.sync.aligned.m8n8.x2.shared.b16 {%0,%1}, [%2];" \
        : "=r"((f)[0]), "=r"((f)[1]) : "r"(addr))
#define MMAF16(d, a, b) \
    asm volatile("mma.sync.aligned.m16n8k16.row.col.f32.f16.f16.f32 " \
        "{%0,%1,%2,%3}, {%4,%5,%6,%7}, {%8,%9}, {%0,%1,%2,%3};" \
        : "+f"((d)[0]), "+f"((d)[1]), "+f"((d)[2]), "+f"((d)[3]) \
        : "r"((a)[0]), "r"((a)[1]), "r"((a)[2]), "r"((a)[3]), \
          "r"((b)[0]), "r"((b)[1]))
#define CP_ASYNC16(dst, src) \
    asm volatile("cp.async.cg.shared.global [%0], [%1], 16;" :: "r"(dst), "l"(src))
#define CP_COMMIT() asm volatile("cp.async.commit_group;" ::: "memory")
#define CP_WAIT0()  asm volatile("cp.async.wait_group 0;"  ::: "memory")
#define CP_WAIT1()  asm volatile("cp.async.wait_group 1;"  ::: "memory")

__device__ __forceinline__ uint32_t h2pack(float a, float b) {
    __half2 t = __floats2half2_rn(a, b);
    return *(uint32_t*)&t;
}
__device__ __forceinline__ float swishf(float h) {
    return h * (1.f / (1.f + __expf(-h)));
}

// -------- kernel 0: W fp32 -> fp16 pre-swizzled tile images -------------
__global__ void wconv_kernel(const float* __restrict__ W) {
    int id = blockIdx.x * 256 + threadIdx.x;   // NTILES*128*NCH*2 ids
    int half = id & 1;
    int ch   = (id >> 1) & (NCH - 1);
    int rr   = id >> 5;                        // global c row (tile*128 + r)
    int r    = rr & 127, tile = rr >> 7;
    bool valid = rr < C_DIM;
    const float* src = W + (size_t)rr * D_K + ch * KC + half * 32;
    unsigned char* base = g_Wh + ((size_t)tile * NCH + ch) * 16384 + r * 128;
    int rot = r & 7;
    #pragma unroll
    for (int j = 0; j < 4; j++) {
        float4 va = valid ? *(const float4*)(src + j * 8)
                          : make_float4(0.f, 0.f, 0.f, 0.f);
        float4 vb = valid ? *(const float4*)(src + j * 8 + 4)
                          : make_float4(0.f, 0.f, 0.f, 0.f);
        uint4 u = make_uint4(h2pack(va.x, va.y), h2pack(va.z, va.w),
                             h2pack(vb.x, vb.y), h2pack(vb.z, vb.w));
        *(uint4*)(base + (((half * 4 + j) ^ rot) << 4)) = u;
    }
}

// ---------------- kernel 1: batch stats (mean, rstd) --------------------
__global__ void stats_kernel(const float* __restrict__ x) {
    int tx = threadIdx.x & 31, ty = threadIdx.x >> 5;
    int c = blockIdx.x * 32 + tx;
    float s = 0.f, sq = 0.f;
    for (int r = ty; r < N_B; r += 8) {
        float v = x[r * D_K + c];
        s += v; sq += v * v;
    }
    __shared__ float ss[8][32], s2[8][32];
    ss[ty][tx] = s; s2[ty][tx] = sq;
    __syncthreads();
    if (ty == 0) {
        #pragma unroll
        for (int j = 1; j < 8; j++) { s += ss[j][tx]; sq += s2[j][tx]; }
        float mean = s * (1.f / N_B);
        float var  = sq * (1.f / N_B) - mean * mean;
        g_mean[c] = mean;
        g_rstd[c] = rsqrtf(var + 1e-5f);
    }
}

// ---------- kernel 2: normalize -> fp16 swizzled B image ----------------
__global__ void bconv_kernel(const float* __restrict__ x) {
    int id = blockIdx.x * 256 + threadIdx.x;   // 8192 threads
    int ch   = id >> 9;
    int m    = (id >> 1) & 255;
    int half = id & 1;
    int kb = ch * KC + half * 32;
    float v[32];
    #pragma unroll
    for (int q = 0; q < 8; q++) {
        float4 a  = *(const float4*)(x + m * D_K + kb + q * 4);
        float4 mu = *(const float4*)(g_mean + kb + q * 4);
        float4 rs = *(const float4*)(g_rstd + kb + q * 4);
        v[q * 4 + 0] = (a.x - mu.x) * rs.x;
        v[q * 4 + 1] = (a.y - mu.y) * rs.y;
        v[q * 4 + 2] = (a.z - mu.z) * rs.z;
        v[q * 4 + 3] = (a.w - mu.w) * rs.w;
    }
    unsigned char* base = g_B + (size_t)ch * (N_B * 128) + m * 128;
    int rot = m & 7;
    #pragma unroll
    for (int j = 0; j < 4; j++) {
        uint4 u = make_uint4(h2pack(v[8 * j + 0], v[8 * j + 1]),
                             h2pack(v[8 * j + 2], v[8 * j + 3]),
                             h2pack(v[8 * j + 4], v[8 * j + 5]),
                             h2pack(v[8 * j + 6], v[8 * j + 7]));
        *(uint4*)(base + (((half * 4 + j) ^ rot) << 4)) = u;
    }
}

// ------- kernel 3: fp16 mma.sync GEMM, bulk 3-stage pipeline ------------
__global__ __launch_bounds__(256, 2) void mma_gemm(const float* __restrict__ bias,
                                                   int m0) {
    extern __shared__ char smem[];
    uint32_t sb = smem_u32(smem);
    int tid = threadIdx.x, lane = tid & 31, warp = tid >> 5;
    int c0 = blockIdx.x * TILE_C;
    int warp_c = warp & 1, warp_m = warp >> 1;

    const unsigned char* gA = g_Wh + (size_t)blockIdx.x * NCH * 16384;
    const unsigned char* gB = g_B + (size_t)m0 * 128;   // per chunk: +ch*32768

    // ldmatrix lane address components
    uint32_t a_row = (uint32_t)(warp_c * 64 + (lane & 7) + ((lane & 8) ? 8 : 0));
    uint32_t a_sel = (lane & 16) ? 16u : 0u;
    uint32_t b_row = (uint32_t)(warp_m * 32 + (lane & 7));
    uint32_t b_sel = (lane & 8) ? 16u : 0u;

    float acc[4][4][4];
    #pragma unroll
    for (int i = 0; i < 4; i++)
        #pragma unroll
        for (int j = 0; j < 4; j++)
            #pragma unroll
            for (int q = 0; q < 4; q++) acc[i][j][q] = 0.f;

    // stage chunk `ch` into buffer slot `s`
    auto stage = [&](int s, int ch) {
        uint32_t dA = sb + s * 32768;
        uint32_t dB = dA + 16384;
        const unsigned char* sA = gA + (size_t)ch * 16384;
        const unsigned char* sB = gB + (size_t)ch * (N_B * 128);
        #pragma unroll
        for (int i = 0; i < 4; i++) {
            int u = (tid + 256 * i) * 16;
            CP_ASYNC16(dA + u, sA + u);
        }
        #pragma unroll
        for (int i = 0; i < 4; i++) {
            int u = (tid + 256 * i) * 16;
            CP_ASYNC16(dB + u, sB + u);
        }
        CP_COMMIT();
    };

    stage(0, 0);
    stage(1, 1);

    for (int ch = 0; ch < NCH; ch++) {
        if (ch < NCH - 2) CP_WAIT1(); else CP_WAIT0();
        __syncthreads();
        if (ch + 2 < NCH) stage((ch + 2) % 3, ch + 2);

        uint32_t Ab = sb + (ch % 3) * 32768;
        uint32_t Bb = Ab + 16384;
        #pragma unroll
        for (int s = 0; s < 4; s++) {
            uint32_t af[4][4], bf[4][2];
            #pragma unroll
            for (int t = 0; t < 4; t++) {
                uint32_t o = (a_row + t * 16) * 128 + s * 32 + a_sel;
                LDSM4(af[t], Ab + SW128(o));
            }
            #pragma unroll
            for (int t = 0; t < 4; t++) {
                uint32_t o = (b_row + t * 8) * 128 + s * 32 + b_sel;
                LDSM2(bf[t], Bb + SW128(o));
            }
            #pragma unroll
            for (int ct = 0; ct < 4; ct++)
                #pragma unroll
                for (int mt = 0; mt < 4; mt++)
                    MMAF16(acc[ct][mt], af[ct], bf[mt]);
        }
        __syncthreads();
    }

    // ---- epilogue: bias + swish -> Zt (fp32) + Zh (fp16) ----
    #pragma unroll
    for (int ct = 0; ct < 4; ct++) {
        int crow = c0 + warp_c * 64 + ct * 16 + (lane >> 2);
        float bv0 = (crow < C_DIM) ? __ldg(bias + crow) : 0.f;
        float bv1 = (crow + 8 < C_DIM) ? __ldg(bias + crow + 8) : 0.f;
        #pragma unroll
        for (int mt = 0; mt < 4; mt++) {
            int m = m0 + warp_m * 32 + mt * 8 + 2 * (lane & 3);
            float* d = acc[ct][mt];
            if (crow < C_DIM) {
                float z0 = swishf(d[0] + bv0), z1 = swishf(d[1] + bv0);
                *(float2*)(g_Zt + (size_t)crow * N_B + m) = make_float2(z0, z1);
                *(uint32_t*)(g_Zh + (size_t)crow * N_B + m) = h2pack(z0, z1);
            }
            if (crow + 8 < C_DIM) {
                float z2 = swishf(d[2] + bv1), z3 = swishf(d[3] + bv1);
                *(float2*)(g_Zt + (size_t)(crow + 8) * N_B + m) =
                    make_float2(z2, z3);
                *(uint32_t*)(g_Zh + (size_t)(crow + 8) * N_B + m) =
                    h2pack(z2, z3);
            }
        }
    }
}

// ---------------- CSR build: zero, hist, scan x3, bucket-scatter --------
__global__ void zero_cnt_kernel() {
    int i = blockIdx.x * 256 + threadIdx.x;
    if (i < C_DIM) g_cnt[i] = 0;
}

__global__ void hist_kernel(const int* __restrict__ A_rows) {
    int e = blockIdx.x * 256 + threadIdx.x;
    if (e < E_TOT) atomicAdd(&g_cnt[A_rows[e]], 1);
}

__global__ void scan1_kernel() {
    int i = blockIdx.x * 256 + threadIdx.x;
    int v = (i < C_DIM) ? g_cnt[i] : 0;
    int lane = threadIdx.x & 31, w = threadIdx.x >> 5;
    int x = v;
    #pragma unroll
    for (int o = 1; o < 32; o <<= 1) {
        int y = __shfl_up_sync(~0u, x, o);
        if (lane >= o) x += y;
    }
    __shared__ int ws[8];
    if (lane == 31) ws[w] = x;
    __syncthreads();
    if (threadIdx.x < 8) {
        int s = ws[threadIdx.x];
        #pragma unroll
        for (int o = 1; o < 8; o <<= 1) {
            int y = __shfl_up_sync(0xff, s, o);
            if ((int)threadIdx.x >= o) s += y;
        }
        ws[threadIdx.x] = s;
    }
    __syncthreads();
    int off = (w > 0) ? ws[w - 1] : 0;
    int incl = x + off;
    if (i < C_DIM) g_local[i] = incl - v;
    if (threadIdx.x == 255) g_bsum[blockIdx.x] = incl;
}

__global__ void scan2_kernel() {
    int i = threadIdx.x;
    int v = (i < NBLK_SCAN) ? g_bsum[i] : 0;
    int lane = i & 31, w = i >> 5;
    int x = v;
    #pragma unroll
    for (int o = 1; o < 32; o <<= 1) {
        int y = __shfl_up_sync(~0u, x, o);
        if (lane >= o) x += y;
    }
    __shared__ int ws[8];
    if (lane == 31) ws[w] = x;
    __syncthreads();
    if (i < 8) {
        int s = ws[i];
        #pragma unroll
        for (int o = 1; o < 8; o <<= 1) {
            int y = __shfl_up_sync(0xff, s, o);
            if (i >= o) s += y;
        }
        ws[i] = s;
    }
    __syncthreads();
    int off = (w > 0) ? ws[w - 1] : 0;
    g_boff[i] = x + off - v;
}

__global__ void scan3_kernel() {
    int i = blockIdx.x * 256 + threadIdx.x;
    if (i < C_DIM) {
        int rs = g_local[i] + g_boff[i >> 8];
        g_rowstart[i] = rs;
        g_cursor[i]   = rs;
    }
    if (i == 0) g_rowstart[C_DIM] = E_TOT;
}

__global__ void build_kernel(const float* __restrict__ A_vals,
                             const float* __restrict__ vec,
                             const int* __restrict__ A_rows,
                             const int* __restrict__ A_cols) {
    int e = blockIdx.x * 256 + threadIdx.x;
    if (e >= E_TOT) return;
    int r = A_rows[e];
    int pos = atomicAdd(&g_cursor[r], 1);
    g_epack[pos] = make_uint2((uint32_t)A_cols[e],
                              __float_as_uint(A_vals[e] * __ldg(&vec[e / NNZ_G])));
}

// -- fused SpMM + transpose-out (one n-half): warp per row, fp16 gather --
__global__ __launch_bounds__(256) void spmm_out_kernel(float* __restrict__ out,
                                                       int nhalf) {
    __shared__ float sm[8][132];
    int wid = threadIdx.x >> 5, lane = threadIdx.x & 31;
    int row = blockIdx.x * 8 + wid;
    int beg = g_rowstart[row], end = g_rowstart[row + 1];
    const uint2* E = g_epack;
    const __half* Zb = g_Zh + nhalf * 128;

    // residual Z init (fp32, exact); lane covers n-local = lane*4 .. +3
    float4 acc = *(const float4*)(g_Zt + (size_t)row * N_B + nhalf * 128 +
                                  lane * 4);

    int e = beg;
    for (; e + 4 <= end; e += 4) {
        uint2 p0 = E[e], p1 = E[e + 1], p2 = E[e + 2], p3 = E[e + 3];
        uint2 h0 = *(const uint2*)(Zb + (size_t)p0.x * N_B + lane * 4);
        uint2 h1 = *(const uint2*)(Zb + (size_t)p1.x * N_B + lane * 4);
        uint2 h2 = *(const uint2*)(Zb + (size_t)p2.x * N_B + lane * 4);
        uint2 h3 = *(const uint2*)(Zb + (size_t)p3.x * N_B + lane * 4);
        float w0 = __uint_as_float(p0.y), w1 = __uint_as_float(p1.y);
        float w2 = __uint_as_float(p2.y), w3 = __uint_as_float(p3.y);
        float2 a, b;
        a = __half22float2(*(__half2*)&h0.x); b = __half22float2(*(__half2*)&h0.y);
        acc.x = fmaf(w0, a.x, acc.x); acc.y = fmaf(w0, a.y, acc.y);
        acc.z = fmaf(w0, b.x, acc.z); acc.w = fmaf(w0, b.y, acc.w);
        a = __half22float2(*(__half2*)&h1.x); b = __half22float2(*(__half2*)&h1.y);
        acc.x = fmaf(w1, a.x, acc.x); acc.y = fmaf(w1, a.y, acc.y);
        acc.z = fmaf(w1, b.x, acc.z); acc.w = fmaf(w1, b.y, acc.w);
        a = __half22float2(*(__half2*)&h2.x); b = __half22float2(*(__half2*)&h2.y);
        acc.x = fmaf(w2, a.x, acc.x); acc.y = fmaf(w2, a.y, acc.y);
        acc.z = fmaf(w2, b.x, acc.z); acc.w = fmaf(w2, b.y, acc.w);
        a = __half22float2(*(__half2*)&h3.x); b = __half22float2(*(__half2*)&h3.y);
        acc.x = fmaf(w3, a.x, acc.x); acc.y = fmaf(w3, a.y, acc.y);
        acc.z = fmaf(w3, b.x, acc.z); acc.w = fmaf(w3, b.y, acc.w);
    }
    for (; e < end; e++) {
        uint2 p = E[e];
        float w = __uint_as_float(p.y);
        uint2 h = *(const uint2*)(Zb + (size_t)p.x * N_B + lane * 4);
        float2 a = __half22float2(*(__half2*)&h.x);
        float2 b = __half22float2(*(__half2*)&h.y);
        acc.x = fmaf(w, a.x, acc.x); acc.y = fmaf(w, a.y, acc.y);
        acc.z = fmaf(w, b.x, acc.z); acc.w = fmaf(w, b.y, acc.w);
    }

    // stage sm[c_local][n_local]
    sm[wid][lane * 4 + 0] = acc.x;
    sm[wid][lane * 4 + 1] = acc.y;
    sm[wid][lane * 4 + 2] = acc.z;
    sm[wid][lane * 4 + 3] = acc.w;
    __syncthreads();

    // transposed write: thread t -> n_local = t>>1, c quad = (t&1)*4
    int nl = threadIdx.x >> 1;
    int cq = (threadIdx.x & 1) * 4;
    float4 v = make_float4(sm[cq + 0][nl], sm[cq + 1][nl],
                           sm[cq + 2][nl], sm[cq + 3][nl]);
    *(float4*)(out + (size_t)(nhalf * 128 + nl) * C_DIM + blockIdx.x * 8 + cq) = v;
}

// ---------------- launch: forked pipeline (gemm0 at kernel index 3) -----
extern "C" void kernel_launch(void* const* d_in, const int* in_sizes, int n_in,
                              void* d_out, int out_size) {
    const float* output = (const float*)d_in[0];
    const float* wt2_w  = (const float*)d_in[1];
    const float* wt2_b  = (const float*)d_in[2];
    const float* A_vals = (const float*)d_in[3];
    const float* vec    = (const float*)d_in[4];
    const int*   A_rows = (const int*)d_in[5];
    const int*   A_cols = (const int*)d_in[6];
    float* out = (float*)d_out;

    static cudaStream_t sCsr = nullptr, sAux = nullptr;
    static cudaEvent_t evFork = nullptr, evCsr = nullptr, evG0 = nullptr,
                       evAux = nullptr;
    if (!sCsr) {
        cudaStreamCreateWithFlags(&sCsr, cudaStreamNonBlocking);
        cudaStreamCreateWithFlags(&sAux, cudaStreamNonBlocking);
        cudaEventCreateWithFlags(&evFork, cudaEventDisableTiming);
        cudaEventCreateWithFlags(&evCsr, cudaEventDisableTiming);
        cudaEventCreateWithFlags(&evG0, cudaEventDisableTiming);
        cudaEventCreateWithFlags(&evAux, cudaEventDisableTiming);
        cudaFuncSetAttribute(mma_gemm,
                             cudaFuncAttributeMaxDynamicSharedMemorySize,
                             GEMM_SMEM);
    }

    int egrid = (E_TOT + 255) / 256;
    int wgrid = (NTILES * 128 * NCH * 2) / 256;   // 6256

    cudaEventRecord(evFork, 0);
    cudaStreamWaitEvent(sCsr, evFork, 0);

    // submission order matters for ncu (-s 5 -c 1 lands on index 3 = gemm0)
    wconv_kernel<<<wgrid, 256>>>(wt2_w);                           // 0
    stats_kernel<<<D_K / 32, 256>>>(output);                       // 1
    bconv_kernel<<<32, 256>>>(output);                             // 2
    mma_gemm<<<NTILES, 256, GEMM_SMEM>>>(wt2_b, 0);                // 3 <- ncu
    cudaEventRecord(evG0, 0);

    zero_cnt_kernel<<<NBLK_SCAN, 256, 0, sCsr>>>();
    hist_kernel<<<egrid, 256, 0, sCsr>>>(A_rows);
    scan1_kernel<<<NBLK_SCAN, 256, 0, sCsr>>>();
    scan2_kernel<<<1, 256, 0, sCsr>>>();
    scan3_kernel<<<NBLK_SCAN, 256, 0, sCsr>>>();
    build_kernel<<<egrid, 256, 0, sCsr>>>(A_vals, vec, A_rows, A_cols);
    cudaEventRecord(evCsr, sCsr);

    mma_gemm<<<NTILES, 256, GEMM_SMEM>>>(wt2_b, 128);

    // aux: half-0 sparse work overlapped with gemm half-1
    cudaStreamWaitEvent(sAux, evG0, 0);
    cudaStreamWaitEvent(sAux, evCsr, 0);
    spmm_out_kernel<<<C_DIM / 8, 256, 0, sAux>>>(out, 0);
    cudaEventRecord(evAux, sAux);

    // main: half-1 sparse work after gemm half-1
    cudaStreamWaitEvent(0, evCsr, 0);
    spmm_out_kernel<<<C_DIM / 8, 256>>>(out, 1);

    cudaStreamWaitEvent(0, evAux, 0);
}